// round 9
// baseline (speedup 1.0000x reference)
#include <cuda_runtime.h>
#include <cuda_bf16.h>

typedef unsigned long long u64;
typedef unsigned int u32;

#define TSTEPS 128
#define NTH    256

// =============== prepped weights (global scratch) ===============
// g_wfrag layout [l][side][part][kt(4)][nt(24)][lane(32)][reg(2)] u32
__device__ __align__(16) u32 g_wfrag[3 * 2 * 2 * 4 * 24 * 32 * 2];   // 73728 u32
// emb: [part][kt(4)][nt(8)][lane][reg] u32
__device__ __align__(16) u32 g_efrag[2 * 4 * 8 * 32 * 2];            // 4096 u32
// combined biases per layer: [0:64)=bir+bhr [64:128)=biz+bhz [128:192)=bin [192:256)=bhn
__device__ __align__(16) float g_bias[3 * 256];

__device__ __forceinline__ u32 packbf(float a, float b) {
    return (u32)__bfloat16_as_ushort(__float2bfloat16(a)) |
           ((u32)__bfloat16_as_ushort(__float2bfloat16(b)) << 16);
}
__device__ __forceinline__ float blo(u32 v) {
    return __bfloat162float(__ushort_as_bfloat16((unsigned short)(v & 0xFFFF)));
}
__device__ __forceinline__ float bhi(u32 v) {
    return __bfloat162float(__ushort_as_bfloat16((unsigned short)(v >> 16)));
}

__global__ void prep_kernel(const float* __restrict__ emb_w,
                            const float* __restrict__ w_ih,
                            const float* __restrict__ w_hh,
                            const float* __restrict__ b_ih,
                            const float* __restrict__ b_hh)
{
    int i0 = blockIdx.x * blockDim.x + threadIdx.x;
    int st = gridDim.x * blockDim.x;
    for (int i = i0; i < 73728; i += st) {
        int reg  = i & 1;
        int lane = (i >> 1) & 31;
        int nt   = (i >> 6) % 24;
        int kt   = (i / 1536) % 4;
        int part = (i / 6144) % 2;
        int side = (i / 12288) % 2;
        int l    = i / 24576;
        int g = lane >> 2, tg = lane & 3;
        int n = nt * 8 + g;
        int k0 = kt * 16 + tg * 2 + reg * 8;
        const float* W = side ? w_hh : w_ih;
        float w0 = W[(l * 192 + n) * 64 + k0];
        float w1 = W[(l * 192 + n) * 64 + k0 + 1];
        if (part == 0) {
            g_wfrag[i] = packbf(w0, w1);
        } else {
            float r0 = w0 - __bfloat162float(__float2bfloat16(w0));
            float r1 = w1 - __bfloat162float(__float2bfloat16(w1));
            g_wfrag[i] = packbf(r0, r1);
        }
    }
    for (int i = i0; i < 4096; i += st) {
        int reg  = i & 1;
        int lane = (i >> 1) & 31;
        int nt   = (i >> 6) & 7;
        int kt   = (i >> 9) & 3;
        int part = i >> 11;
        int g = lane >> 2, tg = lane & 3;
        int n = nt * 8 + g;
        int k0 = kt * 16 + tg * 2 + reg * 8;
        float w0 = emb_w[n * 64 + k0], w1 = emb_w[n * 64 + k0 + 1];
        if (part == 0) {
            g_efrag[i] = packbf(w0, w1);
        } else {
            float r0 = w0 - __bfloat162float(__float2bfloat16(w0));
            float r1 = w1 - __bfloat162float(__float2bfloat16(w1));
            g_efrag[i] = packbf(r0, r1);
        }
    }
    for (int i = i0; i < 3 * 64; i += st) {
        int l = i >> 6, c = i & 63;
        g_bias[l * 256 + c]       = b_ih[l * 192 + c]      + b_hh[l * 192 + c];
        g_bias[l * 256 + 64 + c]  = b_ih[l * 192 + 64 + c] + b_hh[l * 192 + 64 + c];
        g_bias[l * 256 + 128 + c] = b_ih[l * 192 + 128 + c];
        g_bias[l * 256 + 192 + c] = b_hh[l * 192 + 128 + c];
    }
}

// =============== device helpers ===============
__device__ __forceinline__ u32 smem_u32(const void* p) {
    u32 a;
    asm("{ .reg .u64 t; cvta.to.shared.u64 t, %1; cvt.u32.u64 %0, t; }" : "=r"(a) : "l"(p));
    return a;
}
__device__ __forceinline__ void mma16816(float* d, const u32* a, u32 b0, u32 b1) {
    asm volatile(
        "mma.sync.aligned.m16n8k16.row.col.f32.bf16.bf16.f32 "
        "{%0,%1,%2,%3},{%4,%5,%6,%7},{%8,%9},{%0,%1,%2,%3};"
        : "+f"(d[0]), "+f"(d[1]), "+f"(d[2]), "+f"(d[3])
        : "r"(a[0]), "r"(a[1]), "r"(a[2]), "r"(a[3]), "r"(b0), "r"(b1));
}
__device__ __forceinline__ void lds128(u32* r, u32 a) {
    asm volatile("ld.shared.v4.u32 {%0,%1,%2,%3},[%4];"
                 : "=r"(r[0]), "=r"(r[1]), "=r"(r[2]), "=r"(r[3]) : "r"(a));
}
__device__ __forceinline__ void lds64(u32& x, u32& y, u32 a) {
    asm volatile("ld.shared.v2.u32 {%0,%1},[%2];" : "=r"(x), "=r"(y) : "r"(a));
}
__device__ __forceinline__ void sts64(u32 a, u32 x, u32 y) {
    asm volatile("st.shared.v2.u32 [%0],{%1,%2};" :: "r"(a), "r"(x), "r"(y));
}
__device__ __forceinline__ void cpasync16(u32 s, const void* g) {
    asm volatile("cp.async.ca.shared.global [%0],[%1],16;" :: "r"(s), "l"(g));
}
__device__ __forceinline__ void cpcommit() { asm volatile("cp.async.commit_group;"); }
__device__ __forceinline__ void cpwaitall() { asm volatile("cp.async.wait_group 0;"); }
__device__ __forceinline__ float sigmf(float x) { return __fdividef(1.f, 1.f + __expf(-x)); }
__device__ __forceinline__ float tanhfast(float x) { return 1.f - __fdividef(2.f, __expf(2.f * x) + 1.f); }

// SMEM layout (bytes), 64-row CTA:
//   states 0..3 at s*16384 (hi at +0, lo at +8192)    = 65536
//   output partials at SO_P (4mt x 2half x 16 x 2 f32)= 1024
//   weight double-buffer at SO_W: 2 x 24576           = 49152
#define SO_P   65536
#define SO_W   66560
#define WBUF   24576
#define SMEMSZ (SO_W + 2 * WBUF)   /* 115712 -> 2 CTAs/SM = 231424 */

extern "C" __global__ void __launch_bounds__(NTH, 2)
gru_mma_kernel(const float* __restrict__ enc,
               const float* __restrict__ emb_b,
               const float* __restrict__ out_w,
               const float* __restrict__ out_b,
               float* __restrict__ out)
{
    extern __shared__ char smc[];
    const u32 sb   = smem_u32(smc);
    const int tid  = threadIdx.x;
    const int lane = tid & 31;
    const int warp = tid >> 5;            // 8 warps
    const int mt   = warp >> 1;           // 4 mtiles x 16 rows
    const int half = warp & 1;            // column half (32 cols)
    const int g    = lane >> 2;
    const int tg   = lane & 3;
    const int row0 = blockIdx.x * 64;

    // ---- init H0/H1/H2 (states 1..3) frag-linear from enc ----
    for (int i = tid; i < 64 * 32; i += NTH) {
        int m = i >> 5, kp = i & 31;
        int k = kp * 2;
        float v0 = enc[(size_t)(row0 + m) * 64 + k];
        float v1 = enc[(size_t)(row0 + m) * 64 + k + 1];
        u32 hi = packbf(v0, v1);
        u32 lo = packbf(v0 - blo(hi), v1 - bhi(hi));
        int kt = k >> 4, kin = k & 15;
        int gg = m & 15;
        int reg = ((kin >= 8) ? 2 : 0) + ((gg >= 8) ? 1 : 0);
        int ln = (gg & 7) * 4 + ((kin & 7) >> 1);
        u32 off = (u32)((m >> 4) * 2048 + kt * 512 + ln * 16 + reg * 4);
        #pragma unroll
        for (int s = 1; s <= 3; s++) {
            *(u32*)(smc + s * 16384 + off)        = hi;
            *(u32*)(smc + s * 16384 + 8192 + off) = lo;
        }
    }

    // 13 phases: 0 = emb hi+lo (16KB); 1+4l+p = layer l {Wi_hi, Wi_lo, Wh_hi, Wh_lo} (24KB)
    const char* srcs[13]; int szs[13];
    srcs[0] = (const char*)g_efrag; szs[0] = 16384;
    #pragma unroll
    for (int l = 0; l < 3; l++)
        #pragma unroll
        for (int p = 0; p < 4; p++) {
            srcs[1 + 4 * l + p] = (const char*)g_wfrag + l * 98304 + p * 24576;
            szs[1 + 4 * l + p] = 24576;
        }

    // pre-stage phase 0 into buf 0
    for (int o = tid * 16; o < szs[0]; o += NTH * 16)
        cpasync16(sb + SO_W + o, srcs[0] + o);
    cpcommit(); cpwaitall();
    __syncthreads();

    int buf = 0;
    int ph = 0;
    const u32 aoff = (u32)(mt * 2048 + lane * 16);
    float* sp = (float*)(smc + SO_P);

    #pragma unroll 1
    for (int t = 0; t < TSTEPS; t++) {

        // ================= phase 0: embedding =================
        float aE[4][4];
        #pragma unroll
        for (int j = 0; j < 4; j++) { aE[j][0]=0.f; aE[j][1]=0.f; aE[j][2]=0.f; aE[j][3]=0.f; }
        {
            u32 wbn = sb + SO_W + (buf ^ 1) * WBUF;
            for (int o = tid * 16; o < szs[1]; o += NTH * 16)
                cpasync16(wbn + o, srcs[1] + o);
            cpcommit();
        }
        {
            const u32 wb = sb + SO_W + buf * WBUF;
            const u32 abase = sb + 3 * 16384 + aoff;
            #pragma unroll 1
            for (int kt = 0; kt < 4; kt++) {
                u32 ah[4], al[4];
                lds128(ah, abase + (u32)(kt * 512));
                lds128(al, abase + 8192 + (u32)(kt * 512));
                #pragma unroll
                for (int j = 0; j < 4; j++) {
                    int nt = half * 4 + j;
                    u32 ba = wb + (u32)(((kt * 8 + nt) * 32 + lane) * 8);
                    u32 b0, b1;
                    lds64(b0, b1, ba);          // emb hi weights
                    mma16816(aE[j], ah, b0, b1);
                    mma16816(aE[j], al, b0, b1);
                    lds64(b0, b1, ba + 8192);   // emb lo weights
                    mma16816(aE[j], ah, b0, b1);
                }
            }
        }
        cpwaitall(); __syncthreads(); buf ^= 1; ph = 1;

        // emb epilogue -> X (state 0)
        #pragma unroll
        for (int j = 0; j < 4; j++) {
            int ntc = half * 4 + j;
            int c0 = ntc * 8 + 2 * tg;
            float e0 = __ldg(emb_b + c0), e1 = __ldg(emb_b + c0 + 1);
            float x00 = aE[j][0] + e0, x01 = aE[j][1] + e1;
            float x10 = aE[j][2] + e0, x11 = aE[j][3] + e1;
            u32 hi0 = packbf(x00, x01), hi1 = packbf(x10, x11);
            u32 lo0 = packbf(x00 - blo(hi0), x01 - bhi(hi0));
            u32 lo1 = packbf(x10 - blo(hi1), x11 - bhi(hi1));
            u32 ad = sb + (u32)((ntc >> 1) * 512 + (ntc & 1) * 8) + aoff;
            sts64(ad, hi0, hi1);
            sts64(ad + 8192, lo0, lo1);
        }
        __syncthreads();   // X complete before layer-0 MMAs

        // ================= 3 GRU layers =================
        #pragma unroll 1
        for (int l = 0; l < 3; l++) {
            float aR[4][4], aZ[4][4], aN[4][4], aM[4][4];
            #pragma unroll
            for (int j = 0; j < 4; j++)
                #pragma unroll
                for (int q = 0; q < 4; q++) { aR[j][q]=0.f; aZ[j][q]=0.f; aN[j][q]=0.f; aM[j][q]=0.f; }

            #pragma unroll
            for (int p = 0; p < 4; p++) {   // Wi_hi, Wi_lo, Wh_hi, Wh_lo
                {
                    int nx = (ph + 1) % 13;
                    u32 wbn = sb + SO_W + (buf ^ 1) * WBUF;
                    for (int o = tid * 16; o < szs[nx]; o += NTH * 16)
                        cpasync16(wbn + o, srcs[nx] + o);
                    cpcommit();
                }
                const u32 wb = sb + SO_W + buf * WBUF;
                const int stA = (p < 2) ? l : (l + 1);      // x-source or h-source
                const bool hiW = (p & 1) == 0;              // hi-weight phase: 2 terms
                const u32 abase = sb + (u32)(stA * 16384) + aoff;
                #pragma unroll 1
                for (int kt = 0; kt < 4; kt++) {
                    u32 ah[4], al[4];
                    lds128(ah, abase + (u32)(kt * 512));
                    if (hiW) lds128(al, abase + 8192 + (u32)(kt * 512));
                    #pragma unroll
                    for (int gate = 0; gate < 3; gate++) {
                        float (*acc)[4] = (gate == 0) ? aR :
                                          (gate == 1) ? aZ :
                                          ((p < 2) ? aN : aM);
                        #pragma unroll
                        for (int j = 0; j < 4; j++) {
                            int nt = gate * 8 + half * 4 + j;
                            u32 b0, b1;
                            lds64(b0, b1, wb + (u32)(((kt * 24 + nt) * 32 + lane) * 8));
                            mma16816(acc[j], ah, b0, b1);
                            if (hiW) mma16816(acc[j], al, b0, b1);
                        }
                    }
                }
                cpwaitall(); __syncthreads(); buf ^= 1; ph = (ph + 1) % 13;
            }

            // ---- layer epilogue ----
            const float* gb = g_bias + l * 256;
            const u32 hbase = sb + (u32)((l + 1) * 16384) + aoff;
            float oA0 = 0.f, oA1 = 0.f, oB0 = 0.f, oB1 = 0.f;
            #pragma unroll
            for (int j = 0; j < 4; j++) {
                int ntc = half * 4 + j;
                int c0 = ntc * 8 + 2 * tg;
                float br0 = __ldg(gb + c0),        br1 = __ldg(gb + c0 + 1);
                float bz0 = __ldg(gb + 64 + c0),   bz1 = __ldg(gb + 64 + c0 + 1);
                float bn0 = __ldg(gb + 128 + c0),  bn1 = __ldg(gb + 128 + c0 + 1);
                float bm0 = __ldg(gb + 192 + c0),  bm1 = __ldg(gb + 192 + c0 + 1);
                u32 ad = hbase + (u32)((ntc >> 1) * 512 + (ntc & 1) * 8);
                u32 hh0, hh1, hl0, hl1;
                lds64(hh0, hh1, ad);
                lds64(hl0, hl1, ad + 8192);
                float ho00 = blo(hh0) + blo(hl0), ho01 = bhi(hh0) + bhi(hl0);
                float ho10 = blo(hh1) + blo(hl1), ho11 = bhi(hh1) + bhi(hl1);

                float r, z, n;
                r = sigmf(aR[j][0] + br0); z = sigmf(aZ[j][0] + bz0);
                n = tanhfast(aN[j][0] + bn0 + r * (aM[j][0] + bm0));
                float h00 = n + z * (ho00 - n);
                r = sigmf(aR[j][1] + br1); z = sigmf(aZ[j][1] + bz1);
                n = tanhfast(aN[j][1] + bn1 + r * (aM[j][1] + bm1));
                float h01 = n + z * (ho01 - n);
                r = sigmf(aR[j][2] + br0); z = sigmf(aZ[j][2] + bz0);
                n = tanhfast(aN[j][2] + bn0 + r * (aM[j][2] + bm0));
                float h10 = n + z * (ho10 - n);
                r = sigmf(aR[j][3] + br1); z = sigmf(aZ[j][3] + bz1);
                n = tanhfast(aN[j][3] + bn1 + r * (aM[j][3] + bm1));
                float h11 = n + z * (ho11 - n);

                u32 hi0 = packbf(h00, h01), hi1 = packbf(h10, h11);
                u32 lo0 = packbf(h00 - blo(hi0), h01 - bhi(hi0));
                u32 lo1 = packbf(h10 - blo(hi1), h11 - bhi(hi1));
                sts64(ad, hi0, hi1);
                sts64(ad + 8192, lo0, lo1);

                if (l == 2) {
                    float w00 = __ldg(out_w + c0),      w01 = __ldg(out_w + c0 + 1);
                    float w10 = __ldg(out_w + 64 + c0), w11 = __ldg(out_w + 64 + c0 + 1);
                    oA0 += h00 * w00 + h01 * w01;
                    oA1 += h00 * w10 + h01 * w11;
                    oB0 += h10 * w00 + h11 * w01;
                    oB1 += h10 * w10 + h11 * w11;
                }
            }
            if (l == 2) {
                #pragma unroll
                for (int m = 1; m <= 2; m <<= 1) {
                    oA0 += __shfl_xor_sync(0xffffffffu, oA0, m);
                    oA1 += __shfl_xor_sync(0xffffffffu, oA1, m);
                    oB0 += __shfl_xor_sync(0xffffffffu, oB0, m);
                    oB1 += __shfl_xor_sync(0xffffffffu, oB1, m);
                }
                if (tg == 0) {
                    int base = ((mt * 2 + half) * 16 + g) * 2;
                    sp[base]     = oA0;
                    sp[base + 1] = oA1;
                    int base2 = ((mt * 2 + half) * 16 + g + 8) * 2;
                    sp[base2]     = oB0;
                    sp[base2 + 1] = oB1;
                }
            }
            __syncthreads();   // h_l complete before next consumer

            if (l == 2 && half == 0) {
                int row = lane >> 1, j = lane & 1;
                float v = sp[((mt * 2) * 16 + row) * 2 + j] +
                          sp[((mt * 2 + 1) * 16 + row) * 2 + j] + __ldg(out_b + j);
                out[(size_t)(row0 + mt * 16 + row) * (TSTEPS * 2) + t * 2 + j] = v;
            }
        }
    }
}

extern "C" void kernel_launch(void* const* d_in, const int* in_sizes, int n_in,
                              void* d_out, int out_size)
{
    const float* enc   = (const float*)d_in[0];
    const float* emb_w = (const float*)d_in[1];
    const float* emb_b = (const float*)d_in[2];
    const float* w_ih  = (const float*)d_in[3];
    const float* w_hh  = (const float*)d_in[4];
    const float* b_ih  = (const float*)d_in[5];
    const float* b_hh  = (const float*)d_in[6];
    const float* out_w = (const float*)d_in[7];
    const float* out_b = (const float*)d_in[8];

    cudaFuncSetAttribute(gru_mma_kernel,
                         cudaFuncAttributeMaxDynamicSharedMemorySize, SMEMSZ);

    prep_kernel<<<96, 256>>>(emb_w, w_ih, w_hh, b_ih, b_hh);
    gru_mma_kernel<<<256, NTH, SMEMSZ>>>(enc, emb_b, out_w, out_b, (float*)d_out);
}

// round 10
// speedup vs baseline: 1.0575x; 1.0575x over previous
#include <cuda_runtime.h>
#include <cuda_bf16.h>

typedef unsigned long long u64;
typedef unsigned int u32;

#define TSTEPS 128
#define NTH    896
#define MTILE  112
#define NMT    7

// =============== prepped weights (global scratch) ===============
// g_wfrag layout [l][part][side][kt(4)][nt(24)][lane(32)][reg(2)] u32
//   part0=hi part1=lo(residual) ; side0=w_ih side1=w_hh
__device__ __align__(16) u32 g_wfrag[3 * 2 * 2 * 4 * 24 * 32 * 2];   // 73728 u32
// emb: [part][kt(4)][nt(8)][lane][reg] u32
__device__ __align__(16) u32 g_efrag[2 * 4 * 8 * 32 * 2];            // 4096 u32
// combined biases per layer: [0:64)=bir+bhr [64:128)=biz+bhz [128:192)=bin [192:256)=bhn
__device__ __align__(16) float g_bias[3 * 256];

__device__ __forceinline__ u32 packbf(float a, float b) {
    return (u32)__bfloat16_as_ushort(__float2bfloat16(a)) |
           ((u32)__bfloat16_as_ushort(__float2bfloat16(b)) << 16);
}
__device__ __forceinline__ float blo(u32 v) {
    return __bfloat162float(__ushort_as_bfloat16((unsigned short)(v & 0xFFFF)));
}
__device__ __forceinline__ float bhi(u32 v) {
    return __bfloat162float(__ushort_as_bfloat16((unsigned short)(v >> 16)));
}

__global__ void prep_kernel(const float* __restrict__ emb_w,
                            const float* __restrict__ w_ih,
                            const float* __restrict__ w_hh,
                            const float* __restrict__ b_ih,
                            const float* __restrict__ b_hh)
{
    int i0 = blockIdx.x * blockDim.x + threadIdx.x;
    int st = gridDim.x * blockDim.x;
    for (int i = i0; i < 73728; i += st) {
        int reg  = i & 1;
        int lane = (i >> 1) & 31;
        int nt   = (i >> 6) % 24;
        int kt   = (i / 1536) % 4;
        int side = (i / 6144) % 2;
        int part = (i / 12288) % 2;
        int l    = i / 24576;
        int g = lane >> 2, tg = lane & 3;
        int n = nt * 8 + g;
        int k0 = kt * 16 + tg * 2 + reg * 8;
        const float* W = side ? w_hh : w_ih;
        float w0 = W[(l * 192 + n) * 64 + k0];
        float w1 = W[(l * 192 + n) * 64 + k0 + 1];
        if (part == 0) {
            g_wfrag[i] = packbf(w0, w1);
        } else {
            float r0 = w0 - __bfloat162float(__float2bfloat16(w0));
            float r1 = w1 - __bfloat162float(__float2bfloat16(w1));
            g_wfrag[i] = packbf(r0, r1);
        }
    }
    for (int i = i0; i < 4096; i += st) {
        int reg  = i & 1;
        int lane = (i >> 1) & 31;
        int nt   = (i >> 6) & 7;
        int kt   = (i >> 9) & 3;
        int part = i >> 11;
        int g = lane >> 2, tg = lane & 3;
        int n = nt * 8 + g;
        int k0 = kt * 16 + tg * 2 + reg * 8;
        float w0 = emb_w[n * 64 + k0], w1 = emb_w[n * 64 + k0 + 1];
        if (part == 0) {
            g_efrag[i] = packbf(w0, w1);
        } else {
            float r0 = w0 - __bfloat162float(__float2bfloat16(w0));
            float r1 = w1 - __bfloat162float(__float2bfloat16(w1));
            g_efrag[i] = packbf(r0, r1);
        }
    }
    for (int i = i0; i < 3 * 64; i += st) {
        int l = i >> 6, c = i & 63;
        g_bias[l * 256 + c]       = b_ih[l * 192 + c]      + b_hh[l * 192 + c];
        g_bias[l * 256 + 64 + c]  = b_ih[l * 192 + 64 + c] + b_hh[l * 192 + 64 + c];
        g_bias[l * 256 + 128 + c] = b_ih[l * 192 + 128 + c];
        g_bias[l * 256 + 192 + c] = b_hh[l * 192 + 128 + c];
    }
}

// =============== device helpers ===============
__device__ __forceinline__ u32 smem_u32(const void* p) {
    u32 a;
    asm("{ .reg .u64 t; cvta.to.shared.u64 t, %1; cvt.u32.u64 %0, t; }" : "=r"(a) : "l"(p));
    return a;
}
__device__ __forceinline__ void mma16816(float* d, const u32* a, u32 b0, u32 b1) {
    asm volatile(
        "mma.sync.aligned.m16n8k16.row.col.f32.bf16.bf16.f32 "
        "{%0,%1,%2,%3},{%4,%5,%6,%7},{%8,%9},{%0,%1,%2,%3};"
        : "+f"(d[0]), "+f"(d[1]), "+f"(d[2]), "+f"(d[3])
        : "r"(a[0]), "r"(a[1]), "r"(a[2]), "r"(a[3]), "r"(b0), "r"(b1));
}
__device__ __forceinline__ void lds128(u32* r, u32 a) {
    asm volatile("ld.shared.v4.u32 {%0,%1,%2,%3},[%4];"
                 : "=r"(r[0]), "=r"(r[1]), "=r"(r[2]), "=r"(r[3]) : "r"(a));
}
__device__ __forceinline__ void lds64(u32& x, u32& y, u32 a) {
    asm volatile("ld.shared.v2.u32 {%0,%1},[%2];" : "=r"(x), "=r"(y) : "r"(a));
}
__device__ __forceinline__ void sts64(u32 a, u32 x, u32 y) {
    asm volatile("st.shared.v2.u32 [%0],{%1,%2};" :: "r"(a), "r"(x), "r"(y));
}
__device__ __forceinline__ void cpasync16(u32 s, const void* g) {
    asm volatile("cp.async.ca.shared.global [%0],[%1],16;" :: "r"(s), "l"(g));
}
__device__ __forceinline__ void cpcommit() { asm volatile("cp.async.commit_group;"); }
__device__ __forceinline__ void cpwaitall() { asm volatile("cp.async.wait_group 0;"); }
__device__ __forceinline__ float sigmf(float x) { return __fdividef(1.f, 1.f + __expf(-x)); }
__device__ __forceinline__ float tanhfast(float x) { return 1.f - __fdividef(2.f, __expf(2.f * x) + 1.f); }

// SMEM layout (bytes), 112-row CTA:
//   states 0..3 at s*28672 (hi at +0, lo at +14336)   = 114688
//   output partials at SO_P (7mt x 4q x 16 x 2 f32)   = 3584
//   weight double-buffer at SO_W: 2 x 49152           = 98304
#define SO_P   114688
#define SO_W   118272
#define WBUF   49152
#define SMEMSZ (SO_W + 2 * WBUF)   /* 216576 */

extern "C" __global__ void __launch_bounds__(NTH, 1)
gru_mma_kernel(const float* __restrict__ enc,
               const float* __restrict__ emb_b,
               const float* __restrict__ out_w,
               const float* __restrict__ out_b,
               float* __restrict__ out)
{
    extern __shared__ char smc[];
    const u32 sb   = smem_u32(smc);
    const int tid  = threadIdx.x;
    const int lane = tid & 31;
    const int warp = tid >> 5;            // 28 warps
    const int mt   = warp >> 2;           // 7 mtiles x 16 rows
    const int q    = warp & 3;            // column quarter (16 cols of 64)
    const int g    = lane >> 2;
    const int tg   = lane & 3;
    const int row0 = blockIdx.x * MTILE;

    // ---- init H0/H1/H2 (states 1..3) frag-linear from enc (guarded rows) ----
    for (int i = tid; i < MTILE * 32; i += NTH) {
        int m = i >> 5, kp = i & 31;
        int k = kp * 2;
        int rr = row0 + m; if (rr > 16383) rr = 16383;
        float v0 = enc[(size_t)rr * 64 + k];
        float v1 = enc[(size_t)rr * 64 + k + 1];
        u32 hi = packbf(v0, v1);
        u32 lo = packbf(v0 - blo(hi), v1 - bhi(hi));
        int kt = k >> 4, kin = k & 15;
        int gg = m & 15;
        int reg = ((kin >= 8) ? 2 : 0) + ((gg >= 8) ? 1 : 0);
        int ln = (gg & 7) * 4 + ((kin & 7) >> 1);
        u32 off = (u32)((m >> 4) * 2048 + kt * 512 + ln * 16 + reg * 4);
        #pragma unroll
        for (int s = 1; s <= 3; s++) {
            *(u32*)(smc + s * 28672 + off)         = hi;
            *(u32*)(smc + s * 28672 + 14336 + off) = lo;
        }
    }

    // 7 phases: 0 = emb hi+lo (16KB); 1+2l+p = layer l part p (Wi+Wh merged, 48KB)
    const char* srcs[7]; int szs[7];
    srcs[0] = (const char*)g_efrag; szs[0] = 16384;
    #pragma unroll
    for (int l = 0; l < 3; l++)
        #pragma unroll
        for (int p = 0; p < 2; p++) {
            srcs[1 + 2 * l + p] = (const char*)g_wfrag + (l * 2 + p) * 49152;
            szs[1 + 2 * l + p] = 49152;
        }

    // pre-stage phase 0 into buf 0
    for (int o = tid * 16; o < szs[0]; o += NTH * 16)
        cpasync16(sb + SO_W + o, srcs[0] + o);
    cpcommit(); cpwaitall();
    __syncthreads();

    int buf = 0;
    int ph = 0;
    const u32 aoff = (u32)(mt * 2048 + lane * 16);
    float* sp = (float*)(smc + SO_P);

    #pragma unroll 1
    for (int t = 0; t < TSTEPS; t++) {

        // ================= phase 0: embedding =================
        float aE[2][4];
        #pragma unroll
        for (int j = 0; j < 2; j++) { aE[j][0]=0.f; aE[j][1]=0.f; aE[j][2]=0.f; aE[j][3]=0.f; }
        {
            u32 wbn = sb + SO_W + (buf ^ 1) * WBUF;
            for (int o = tid * 16; o < szs[1]; o += NTH * 16)
                cpasync16(wbn + o, srcs[1] + o);
            cpcommit();
        }
        {
            const u32 wb = sb + SO_W + buf * WBUF;
            const u32 abase = sb + 3 * 28672 + aoff;
            #pragma unroll 1
            for (int kt = 0; kt < 4; kt++) {
                u32 ah[4], al[4];
                lds128(ah, abase + (u32)(kt * 512));
                lds128(al, abase + 14336 + (u32)(kt * 512));
                #pragma unroll
                for (int j = 0; j < 2; j++) {
                    int nt = q * 2 + j;
                    u32 ba = wb + (u32)(((kt * 8 + nt) * 32 + lane) * 8);
                    u32 b0, b1;
                    lds64(b0, b1, ba);          // emb hi weights
                    mma16816(aE[j], ah, b0, b1);
                    mma16816(aE[j], al, b0, b1);
                    lds64(b0, b1, ba + 8192);   // emb lo weights
                    mma16816(aE[j], ah, b0, b1);
                }
            }
        }
        cpwaitall(); __syncthreads(); buf ^= 1; ph = 1;

        // emb epilogue -> X (state 0), own 16 cols
        #pragma unroll
        for (int j = 0; j < 2; j++) {
            int ntc = q * 2 + j;
            int c0 = ntc * 8 + 2 * tg;
            float e0 = __ldg(emb_b + c0), e1 = __ldg(emb_b + c0 + 1);
            float x00 = aE[j][0] + e0, x01 = aE[j][1] + e1;
            float x10 = aE[j][2] + e0, x11 = aE[j][3] + e1;
            u32 hi0 = packbf(x00, x01), hi1 = packbf(x10, x11);
            u32 lo0 = packbf(x00 - blo(hi0), x01 - bhi(hi0));
            u32 lo1 = packbf(x10 - blo(hi1), x11 - bhi(hi1));
            u32 ad = sb + (u32)((ntc >> 1) * 512 + (ntc & 1) * 8) + aoff;
            sts64(ad, hi0, hi1);
            sts64(ad + 14336, lo0, lo1);
        }
        __syncthreads();   // X complete before layer-0 MMAs

        // ================= 3 GRU layers =================
        #pragma unroll 1
        for (int l = 0; l < 3; l++) {
            float aR[2][4], aZ[2][4], aN[2][4], aM[2][4];
            #pragma unroll
            for (int j = 0; j < 2; j++)
                #pragma unroll
                for (int e = 0; e < 4; e++) { aR[j][e]=0.f; aZ[j][e]=0.f; aN[j][e]=0.f; aM[j][e]=0.f; }

            #pragma unroll
            for (int p = 0; p < 2; p++) {   // p0 = hi weights (2 A-terms), p1 = lo weights (1 A-term)
                {
                    int nx = (ph + 1) % 7;
                    u32 wbn = sb + SO_W + (buf ^ 1) * WBUF;
                    for (int o = tid * 16; o < szs[nx]; o += NTH * 16)
                        cpasync16(wbn + o, srcs[nx] + o);
                    cpcommit();
                }
                const u32 wb = sb + SO_W + buf * WBUF;
                const bool hiW = (p == 0);
                #pragma unroll
                for (int side = 0; side < 2; side++) {    // 0 = x*Wi, 1 = h*Wh
                    const int stA = (side == 0) ? l : (l + 1);
                    const u32 abase = sb + (u32)(stA * 28672) + aoff;
                    const u32 wside = wb + (u32)(side * 24576);
                    #pragma unroll 1
                    for (int kt = 0; kt < 4; kt++) {
                        u32 ah[4], al[4];
                        lds128(ah, abase + (u32)(kt * 512));
                        if (hiW) lds128(al, abase + 14336 + (u32)(kt * 512));
                        #pragma unroll
                        for (int gate = 0; gate < 3; gate++) {
                            float (*acc)[4] = (gate == 0) ? aR :
                                              (gate == 1) ? aZ :
                                              ((side == 0) ? aN : aM);
                            #pragma unroll
                            for (int j = 0; j < 2; j++) {
                                int nt = gate * 8 + q * 2 + j;
                                u32 b0, b1;
                                lds64(b0, b1, wside + (u32)(((kt * 24 + nt) * 32 + lane) * 8));
                                mma16816(acc[j], ah, b0, b1);
                                if (hiW) mma16816(acc[j], al, b0, b1);
                            }
                        }
                    }
                }
                cpwaitall(); __syncthreads(); buf ^= 1; ph = (ph + 1) % 7;
            }

            // ---- layer epilogue ----
            const float* gb = g_bias + l * 256;
            const u32 hbase = sb + (u32)((l + 1) * 28672) + aoff;
            float oA0 = 0.f, oA1 = 0.f, oB0 = 0.f, oB1 = 0.f;
            #pragma unroll
            for (int j = 0; j < 2; j++) {
                int ntc = q * 2 + j;
                int c0 = ntc * 8 + 2 * tg;
                float br0 = __ldg(gb + c0),        br1 = __ldg(gb + c0 + 1);
                float bz0 = __ldg(gb + 64 + c0),   bz1 = __ldg(gb + 64 + c0 + 1);
                float bn0 = __ldg(gb + 128 + c0),  bn1 = __ldg(gb + 128 + c0 + 1);
                float bm0 = __ldg(gb + 192 + c0),  bm1 = __ldg(gb + 192 + c0 + 1);
                u32 ad = hbase + (u32)((ntc >> 1) * 512 + (ntc & 1) * 8);
                u32 hh0, hh1, hl0, hl1;
                lds64(hh0, hh1, ad);
                lds64(hl0, hl1, ad + 14336);
                float ho00 = blo(hh0) + blo(hl0), ho01 = bhi(hh0) + bhi(hl0);
                float ho10 = blo(hh1) + blo(hl1), ho11 = bhi(hh1) + bhi(hl1);

                float r, z, n;
                r = sigmf(aR[j][0] + br0); z = sigmf(aZ[j][0] + bz0);
                n = tanhfast(aN[j][0] + bn0 + r * (aM[j][0] + bm0));
                float h00 = n + z * (ho00 - n);
                r = sigmf(aR[j][1] + br1); z = sigmf(aZ[j][1] + bz1);
                n = tanhfast(aN[j][1] + bn1 + r * (aM[j][1] + bm1));
                float h01 = n + z * (ho01 - n);
                r = sigmf(aR[j][2] + br0); z = sigmf(aZ[j][2] + bz0);
                n = tanhfast(aN[j][2] + bn0 + r * (aM[j][2] + bm0));
                float h10 = n + z * (ho10 - n);
                r = sigmf(aR[j][3] + br1); z = sigmf(aZ[j][3] + bz1);
                n = tanhfast(aN[j][3] + bn1 + r * (aM[j][3] + bm1));
                float h11 = n + z * (ho11 - n);

                u32 hi0 = packbf(h00, h01), hi1 = packbf(h10, h11);
                u32 lo0 = packbf(h00 - blo(hi0), h01 - bhi(hi0));
                u32 lo1 = packbf(h10 - blo(hi1), h11 - bhi(hi1));
                sts64(ad, hi0, hi1);
                sts64(ad + 14336, lo0, lo1);

                if (l == 2) {
                    float w00 = __ldg(out_w + c0),      w01 = __ldg(out_w + c0 + 1);
                    float w10 = __ldg(out_w + 64 + c0), w11 = __ldg(out_w + 64 + c0 + 1);
                    oA0 += h00 * w00 + h01 * w01;
                    oA1 += h00 * w10 + h01 * w11;
                    oB0 += h10 * w00 + h11 * w01;
                    oB1 += h10 * w10 + h11 * w11;
                }
            }
            if (l == 2) {
                #pragma unroll
                for (int m = 1; m <= 2; m <<= 1) {
                    oA0 += __shfl_xor_sync(0xffffffffu, oA0, m);
                    oA1 += __shfl_xor_sync(0xffffffffu, oA1, m);
                    oB0 += __shfl_xor_sync(0xffffffffu, oB0, m);
                    oB1 += __shfl_xor_sync(0xffffffffu, oB1, m);
                }
                if (tg == 0) {
                    int base = ((mt * 4 + q) * 16 + g) * 2;
                    sp[base]     = oA0;
                    sp[base + 1] = oA1;
                    int base2 = ((mt * 4 + q) * 16 + g + 8) * 2;
                    sp[base2]     = oB0;
                    sp[base2 + 1] = oB1;
                }
            }
            __syncthreads();   // h_l complete before next consumer

            if (l == 2 && q == 0) {
                int row = lane >> 1, j = lane & 1;
                float v = sp[((mt * 4 + 0) * 16 + row) * 2 + j] +
                          sp[((mt * 4 + 1) * 16 + row) * 2 + j] +
                          sp[((mt * 4 + 2) * 16 + row) * 2 + j] +
                          sp[((mt * 4 + 3) * 16 + row) * 2 + j] + __ldg(out_b + j);
                int grow = row0 + mt * 16 + row;
                if (grow < 16384)
                    out[(size_t)grow * (TSTEPS * 2) + t * 2 + j] = v;
            }
        }
    }
}

extern "C" void kernel_launch(void* const* d_in, const int* in_sizes, int n_in,
                              void* d_out, int out_size)
{
    const float* enc   = (const float*)d_in[0];
    const float* emb_w = (const float*)d_in[1];
    const float* emb_b = (const float*)d_in[2];
    const float* w_ih  = (const float*)d_in[3];
    const float* w_hh  = (const float*)d_in[4];
    const float* b_ih  = (const float*)d_in[5];
    const float* b_hh  = (const float*)d_in[6];
    const float* out_w = (const float*)d_in[7];
    const float* out_b = (const float*)d_in[8];

    cudaFuncSetAttribute(gru_mma_kernel,
                         cudaFuncAttributeMaxDynamicSharedMemorySize, SMEMSZ);

    prep_kernel<<<96, 256>>>(emb_w, w_ih, w_hh, b_ih, b_hh);
    gru_mma_kernel<<<152, NTH, SMEMSZ>>>(enc, emb_b, out_w, out_b, (float*)d_out);
}

// round 11
// speedup vs baseline: 1.5266x; 1.4437x over previous
#include <cuda_runtime.h>
#include <cuda_bf16.h>

typedef unsigned long long u64;
typedef unsigned int u32;

#define TSTEPS 128
#define NTH    896
#define MTILE  112

// =============== prepped weights (global scratch), hi(bf16) only ===============
// g_wh layout [l][side][kt(4)][nt(24)][lane(32)][reg(2)] u32 ; side0=w_ih side1=w_hh
__device__ __align__(16) u32 g_wh[3 * 2 * 4 * 24 * 32 * 2];   // 36864 u32 (147456 B)
// emb hi: [kt(4)][nt(8)][lane][reg] u32
__device__ __align__(16) u32 g_eh[4 * 8 * 32 * 2];            // 2048 u32 (8192 B)
// combined biases per layer: [0:64)=bir+bhr [64:128)=biz+bhz [128:192)=bin [192:256)=bhn
__device__ __align__(16) float g_bias[3 * 256];

__device__ __forceinline__ u32 packbf(float a, float b) {
    return (u32)__bfloat16_as_ushort(__float2bfloat16(a)) |
           ((u32)__bfloat16_as_ushort(__float2bfloat16(b)) << 16);
}
__device__ __forceinline__ float blo(u32 v) {
    return __bfloat162float(__ushort_as_bfloat16((unsigned short)(v & 0xFFFF)));
}
__device__ __forceinline__ float bhi(u32 v) {
    return __bfloat162float(__ushort_as_bfloat16((unsigned short)(v >> 16)));
}

__global__ void prep_kernel(const float* __restrict__ emb_w,
                            const float* __restrict__ w_ih,
                            const float* __restrict__ w_hh,
                            const float* __restrict__ b_ih,
                            const float* __restrict__ b_hh)
{
    int i0 = blockIdx.x * blockDim.x + threadIdx.x;
    int st = gridDim.x * blockDim.x;
    for (int i = i0; i < 36864; i += st) {
        int reg  = i & 1;
        int lane = (i >> 1) & 31;
        int nt   = (i >> 6) % 24;
        int kt   = (i / 1536) % 4;
        int side = (i / 6144) % 2;
        int l    = i / 12288;
        int g = lane >> 2, tg = lane & 3;
        int n = nt * 8 + g;
        int k0 = kt * 16 + tg * 2 + reg * 8;
        const float* W = side ? w_hh : w_ih;
        g_wh[i] = packbf(W[(l * 192 + n) * 64 + k0], W[(l * 192 + n) * 64 + k0 + 1]);
    }
    for (int i = i0; i < 2048; i += st) {
        int reg  = i & 1;
        int lane = (i >> 1) & 31;
        int nt   = (i >> 6) & 7;
        int kt   = (i >> 9) & 3;
        int g = lane >> 2, tg = lane & 3;
        int n = nt * 8 + g;
        int k0 = kt * 16 + tg * 2 + reg * 8;
        g_eh[i] = packbf(emb_w[n * 64 + k0], emb_w[n * 64 + k0 + 1]);
    }
    for (int i = i0; i < 3 * 64; i += st) {
        int l = i >> 6, c = i & 63;
        g_bias[l * 256 + c]       = b_ih[l * 192 + c]      + b_hh[l * 192 + c];
        g_bias[l * 256 + 64 + c]  = b_ih[l * 192 + 64 + c] + b_hh[l * 192 + 64 + c];
        g_bias[l * 256 + 128 + c] = b_ih[l * 192 + 128 + c];
        g_bias[l * 256 + 192 + c] = b_hh[l * 192 + 128 + c];
    }
}

// =============== device helpers ===============
__device__ __forceinline__ u32 smem_u32(const void* p) {
    u32 a;
    asm("{ .reg .u64 t; cvta.to.shared.u64 t, %1; cvt.u32.u64 %0, t; }" : "=r"(a) : "l"(p));
    return a;
}
__device__ __forceinline__ void mma16816(float* d, const u32* a, u32 b0, u32 b1) {
    asm volatile(
        "mma.sync.aligned.m16n8k16.row.col.f32.bf16.bf16.f32 "
        "{%0,%1,%2,%3},{%4,%5,%6,%7},{%8,%9},{%0,%1,%2,%3};"
        : "+f"(d[0]), "+f"(d[1]), "+f"(d[2]), "+f"(d[3])
        : "r"(a[0]), "r"(a[1]), "r"(a[2]), "r"(a[3]), "r"(b0), "r"(b1));
}
__device__ __forceinline__ void lds128(u32* r, u32 a) {
    asm volatile("ld.shared.v4.u32 {%0,%1,%2,%3},[%4];"
                 : "=r"(r[0]), "=r"(r[1]), "=r"(r[2]), "=r"(r[3]) : "r"(a));
}
__device__ __forceinline__ void lds64(u32& x, u32& y, u32 a) {
    asm volatile("ld.shared.v2.u32 {%0,%1},[%2];" : "=r"(x), "=r"(y) : "r"(a));
}
__device__ __forceinline__ void sts64(u32 a, u32 x, u32 y) {
    asm volatile("st.shared.v2.u32 [%0],{%1,%2};" :: "r"(a), "r"(x), "r"(y));
}
__device__ __forceinline__ void cpasync16(u32 s, const void* g) {
    asm volatile("cp.async.ca.shared.global [%0],[%1],16;" :: "r"(s), "l"(g));
}
__device__ __forceinline__ void cpcommit() { asm volatile("cp.async.commit_group;"); }
__device__ __forceinline__ void cpwaitall() { asm volatile("cp.async.wait_group 0;"); }
__device__ __forceinline__ float sigmf(float x) { return __fdividef(1.f, 1.f + __expf(-x)); }
__device__ __forceinline__ float tanhfast(float x) { return 1.f - __fdividef(2.f, __expf(2.f * x) + 1.f); }

// SMEM layout (bytes), 112-row CTA:
//   states 0..3 at s*28672 (hi at +0, lo at +14336)   = 114688
//   output partials at SO_P (7mt x 4q x 16 x 2 f32)   = 3584
//   weight double-buffer at SO_W: 2 x 49152           = 98304
#define SO_P   114688
#define SO_W   118272
#define WBUF   49152
#define SMEMSZ (SO_W + 2 * WBUF)   /* 216576 */

extern "C" __global__ void __launch_bounds__(NTH, 1)
gru_mma_kernel(const float* __restrict__ enc,
               const float* __restrict__ emb_b,
               const float* __restrict__ out_w,
               const float* __restrict__ out_b,
               float* __restrict__ out)
{
    extern __shared__ char smc[];
    const u32 sb   = smem_u32(smc);
    const int tid  = threadIdx.x;
    const int lane = tid & 31;
    const int warp = tid >> 5;            // 28 warps
    const int mt   = warp >> 2;           // 7 mtiles x 16 rows
    const int q    = warp & 3;            // column quarter (16 cols of 64)
    const int g    = lane >> 2;
    const int tg   = lane & 3;
    const int row0 = blockIdx.x * MTILE;

    // ---- init H0/H1/H2 (states 1..3) frag-linear from enc (guarded rows) ----
    for (int i = tid; i < MTILE * 32; i += NTH) {
        int m = i >> 5, kp = i & 31;
        int k = kp * 2;
        int rr = row0 + m; if (rr > 16383) rr = 16383;
        float v0 = enc[(size_t)rr * 64 + k];
        float v1 = enc[(size_t)rr * 64 + k + 1];
        u32 hi = packbf(v0, v1);
        u32 lo = packbf(v0 - blo(hi), v1 - bhi(hi));
        int kt = k >> 4, kin = k & 15;
        int gg = m & 15;
        int reg = ((kin >= 8) ? 2 : 0) + ((gg >= 8) ? 1 : 0);
        int ln = (gg & 7) * 4 + ((kin & 7) >> 1);
        u32 off = (u32)((m >> 4) * 2048 + kt * 512 + ln * 16 + reg * 4);
        #pragma unroll
        for (int s = 1; s <= 3; s++) {
            *(u32*)(smc + s * 28672 + off)         = hi;
            *(u32*)(smc + s * 28672 + 14336 + off) = lo;
        }
    }

    // 4 phases: 0 = emb hi (8KB); 1+l = layer l (Wi_hi + Wh_hi, 48KB)
    const char* srcs[4]; int szs[4];
    srcs[0] = (const char*)g_eh; szs[0] = 8192;
    #pragma unroll
    for (int l = 0; l < 3; l++) {
        srcs[1 + l] = (const char*)g_wh + l * 49152;
        szs[1 + l] = 49152;
    }

    // pre-stage phase 0 into buf 0
    for (int o = tid * 16; o < szs[0]; o += NTH * 16)
        cpasync16(sb + SO_W + o, srcs[0] + o);
    cpcommit(); cpwaitall();
    __syncthreads();

    int buf = 0;
    int ph = 0;
    const u32 aoff = (u32)(mt * 2048 + lane * 16);
    float* sp = (float*)(smc + SO_P);

    #pragma unroll 1
    for (int t = 0; t < TSTEPS; t++) {

        // ================= phase 0: embedding =================
        float aE[2][4];
        #pragma unroll
        for (int j = 0; j < 2; j++) { aE[j][0]=0.f; aE[j][1]=0.f; aE[j][2]=0.f; aE[j][3]=0.f; }
        {
            u32 wbn = sb + SO_W + (buf ^ 1) * WBUF;
            for (int o = tid * 16; o < szs[1]; o += NTH * 16)
                cpasync16(wbn + o, srcs[1] + o);
            cpcommit();
        }
        {
            const u32 wb = sb + SO_W + buf * WBUF;
            const u32 abase = sb + 3 * 28672 + aoff;
            #pragma unroll 1
            for (int kt = 0; kt < 4; kt++) {
                u32 ah[4], al[4];
                lds128(ah, abase + (u32)(kt * 512));
                lds128(al, abase + 14336 + (u32)(kt * 512));
                #pragma unroll
                for (int j = 0; j < 2; j++) {
                    int nt = q * 2 + j;
                    u32 b0, b1;
                    lds64(b0, b1, wb + (u32)(((kt * 8 + nt) * 32 + lane) * 8));
                    mma16816(aE[j], ah, b0, b1);
                    mma16816(aE[j], al, b0, b1);
                }
            }
        }
        cpwaitall(); __syncthreads(); buf ^= 1; ph = 1;

        // emb epilogue -> X (state 0), own 16 cols
        #pragma unroll
        for (int j = 0; j < 2; j++) {
            int ntc = q * 2 + j;
            int c0 = ntc * 8 + 2 * tg;
            float e0 = __ldg(emb_b + c0), e1 = __ldg(emb_b + c0 + 1);
            float x00 = aE[j][0] + e0, x01 = aE[j][1] + e1;
            float x10 = aE[j][2] + e0, x11 = aE[j][3] + e1;
            u32 hi0 = packbf(x00, x01), hi1 = packbf(x10, x11);
            u32 lo0 = packbf(x00 - blo(hi0), x01 - bhi(hi0));
            u32 lo1 = packbf(x10 - blo(hi1), x11 - bhi(hi1));
            u32 ad = sb + (u32)((ntc >> 1) * 512 + (ntc & 1) * 8) + aoff;
            sts64(ad, hi0, hi1);
            sts64(ad + 14336, lo0, lo1);
        }
        __syncthreads();   // X complete before layer-0 MMAs

        // ================= 3 GRU layers =================
        #pragma unroll 1
        for (int l = 0; l < 3; l++) {
            float aR[2][4], aZ[2][4], aN[2][4], aM[2][4];
            #pragma unroll
            for (int j = 0; j < 2; j++)
                #pragma unroll
                for (int e = 0; e < 4; e++) { aR[j][e]=0.f; aZ[j][e]=0.f; aN[j][e]=0.f; aM[j][e]=0.f; }

            {
                int nx = (ph + 1) & 3;
                u32 wbn = sb + SO_W + (buf ^ 1) * WBUF;
                for (int o = tid * 16; o < szs[nx]; o += NTH * 16)
                    cpasync16(wbn + o, srcs[nx] + o);
                cpcommit();
            }
            {
                const u32 wb = sb + SO_W + buf * WBUF;
                #pragma unroll
                for (int side = 0; side < 2; side++) {    // 0 = x*Wi, 1 = h*Wh
                    const int stA = (side == 0) ? l : (l + 1);
                    const u32 abase = sb + (u32)(stA * 28672) + aoff;
                    const u32 wside = wb + (u32)(side * 24576);
                    #pragma unroll 1
                    for (int kt = 0; kt < 4; kt++) {
                        u32 ah[4], al[4];
                        lds128(ah, abase + (u32)(kt * 512));
                        lds128(al, abase + 14336 + (u32)(kt * 512));
                        #pragma unroll
                        for (int gate = 0; gate < 3; gate++) {
                            float (*acc)[4] = (gate == 0) ? aR :
                                              (gate == 1) ? aZ :
                                              ((side == 0) ? aN : aM);
                            #pragma unroll
                            for (int j = 0; j < 2; j++) {
                                int nt = gate * 8 + q * 2 + j;
                                u32 b0, b1;
                                lds64(b0, b1, wside + (u32)(((kt * 24 + nt) * 32 + lane) * 8));
                                mma16816(acc[j], ah, b0, b1);
                                mma16816(acc[j], al, b0, b1);
                            }
                        }
                    }
                }
            }
            cpwaitall(); __syncthreads(); buf ^= 1; ph = (ph + 1) & 3;

            // ---- layer epilogue ----
            const float* gb = g_bias + l * 256;
            const u32 hbase = sb + (u32)((l + 1) * 28672) + aoff;
            float oA0 = 0.f, oA1 = 0.f, oB0 = 0.f, oB1 = 0.f;
            #pragma unroll
            for (int j = 0; j < 2; j++) {
                int ntc = q * 2 + j;
                int c0 = ntc * 8 + 2 * tg;
                float br0 = __ldg(gb + c0),        br1 = __ldg(gb + c0 + 1);
                float bz0 = __ldg(gb + 64 + c0),   bz1 = __ldg(gb + 64 + c0 + 1);
                float bn0 = __ldg(gb + 128 + c0),  bn1 = __ldg(gb + 128 + c0 + 1);
                float bm0 = __ldg(gb + 192 + c0),  bm1 = __ldg(gb + 192 + c0 + 1);
                u32 ad = hbase + (u32)((ntc >> 1) * 512 + (ntc & 1) * 8);
                u32 hh0, hh1, hl0, hl1;
                lds64(hh0, hh1, ad);
                lds64(hl0, hl1, ad + 14336);
                float ho00 = blo(hh0) + blo(hl0), ho01 = bhi(hh0) + bhi(hl0);
                float ho10 = blo(hh1) + blo(hl1), ho11 = bhi(hh1) + bhi(hl1);

                float r, z, n;
                r = sigmf(aR[j][0] + br0); z = sigmf(aZ[j][0] + bz0);
                n = tanhfast(aN[j][0] + bn0 + r * (aM[j][0] + bm0));
                float h00 = n + z * (ho00 - n);
                r = sigmf(aR[j][1] + br1); z = sigmf(aZ[j][1] + bz1);
                n = tanhfast(aN[j][1] + bn1 + r * (aM[j][1] + bm1));
                float h01 = n + z * (ho01 - n);
                r = sigmf(aR[j][2] + br0); z = sigmf(aZ[j][2] + bz0);
                n = tanhfast(aN[j][2] + bn0 + r * (aM[j][2] + bm0));
                float h10 = n + z * (ho10 - n);
                r = sigmf(aR[j][3] + br1); z = sigmf(aZ[j][3] + bz1);
                n = tanhfast(aN[j][3] + bn1 + r * (aM[j][3] + bm1));
                float h11 = n + z * (ho11 - n);

                u32 hi0 = packbf(h00, h01), hi1 = packbf(h10, h11);
                u32 lo0 = packbf(h00 - blo(hi0), h01 - bhi(hi0));
                u32 lo1 = packbf(h10 - blo(hi1), h11 - bhi(hi1));
                sts64(ad, hi0, hi1);
                sts64(ad + 14336, lo0, lo1);

                if (l == 2) {
                    float w00 = __ldg(out_w + c0),      w01 = __ldg(out_w + c0 + 1);
                    float w10 = __ldg(out_w + 64 + c0), w11 = __ldg(out_w + 64 + c0 + 1);
                    oA0 += h00 * w00 + h01 * w01;
                    oA1 += h00 * w10 + h01 * w11;
                    oB0 += h10 * w00 + h11 * w01;
                    oB1 += h10 * w10 + h11 * w11;
                }
            }
            if (l == 2) {
                #pragma unroll
                for (int m = 1; m <= 2; m <<= 1) {
                    oA0 += __shfl_xor_sync(0xffffffffu, oA0, m);
                    oA1 += __shfl_xor_sync(0xffffffffu, oA1, m);
                    oB0 += __shfl_xor_sync(0xffffffffu, oB0, m);
                    oB1 += __shfl_xor_sync(0xffffffffu, oB1, m);
                }
                if (tg == 0) {
                    int base = ((mt * 4 + q) * 16 + g) * 2;
                    sp[base]     = oA0;
                    sp[base + 1] = oA1;
                    int base2 = ((mt * 4 + q) * 16 + g + 8) * 2;
                    sp[base2]     = oB0;
                    sp[base2 + 1] = oB1;
                }
            }
            __syncthreads();   // h_l complete before next consumer

            if (l == 2 && q == 0) {
                int row = lane >> 1, j = lane & 1;
                float v = sp[((mt * 4 + 0) * 16 + row) * 2 + j] +
                          sp[((mt * 4 + 1) * 16 + row) * 2 + j] +
                          sp[((mt * 4 + 2) * 16 + row) * 2 + j] +
                          sp[((mt * 4 + 3) * 16 + row) * 2 + j] + __ldg(out_b + j);
                int grow = row0 + mt * 16 + row;
                if (grow < 16384)
                    out[(size_t)grow * (TSTEPS * 2) + t * 2 + j] = v;
            }
        }
    }
}

extern "C" void kernel_launch(void* const* d_in, const int* in_sizes, int n_in,
                              void* d_out, int out_size)
{
    const float* enc   = (const float*)d_in[0];
    const float* emb_w = (const float*)d_in[1];
    const float* emb_b = (const float*)d_in[2];
    const float* w_ih  = (const float*)d_in[3];
    const float* w_hh  = (const float*)d_in[4];
    const float* b_ih  = (const float*)d_in[5];
    const float* b_hh  = (const float*)d_in[6];
    const float* out_w = (const float*)d_in[7];
    const float* out_b = (const float*)d_in[8];

    cudaFuncSetAttribute(gru_mma_kernel,
                         cudaFuncAttributeMaxDynamicSharedMemorySize, SMEMSZ);

    prep_kernel<<<96, 256>>>(emb_w, w_ih, w_hh, b_ih, b_hh);
    gru_mma_kernel<<<152, NTH, SMEMSZ>>>(enc, emb_b, out_w, out_b, (float*)d_out);
}

// round 12
// speedup vs baseline: 1.8789x; 1.2308x over previous
#include <cuda_runtime.h>
#include <cuda_bf16.h>

typedef unsigned long long u64;
typedef unsigned int u32;

#define TSTEPS 128
#define NTH    896
#define MTILE  112

// =============== prepped weights (global scratch), bf16-hi only ===============
// g_wh layout [l][side][kt(4)][gate(3)][q(4)][lane(32)][j(2)][reg(2)] u32
//   side0 = x-side weights (layer0: fused Wi0@We), side1 = w_hh
__device__ __align__(16) u32 g_wh[3 * 2 * 4 * 3 * 4 * 32 * 2 * 2];   // 36864 u32
// combined biases per layer: [0:64)=bir+bhr(+bf_r) [64:128)=biz+bhz(+bf_z)
//                            [128:192)=bin(+bf_n)  [192:256)=bhn
__device__ __align__(16) float g_bias[3 * 256];

__device__ __forceinline__ u32 packbf(float a, float b) {
    return (u32)__bfloat16_as_ushort(__float2bfloat16(a)) |
           ((u32)__bfloat16_as_ushort(__float2bfloat16(b)) << 16);
}
__device__ __forceinline__ float blo(u32 v) {
    return __bfloat162float(__ushort_as_bfloat16((unsigned short)(v & 0xFFFF)));
}
__device__ __forceinline__ float bhi(u32 v) {
    return __bfloat162float(__ushort_as_bfloat16((unsigned short)(v >> 16)));
}

__global__ void prep_kernel(const float* __restrict__ emb_w,
                            const float* __restrict__ emb_b,
                            const float* __restrict__ w_ih,
                            const float* __restrict__ w_hh,
                            const float* __restrict__ b_ih,
                            const float* __restrict__ b_hh)
{
    int i0 = blockIdx.x * blockDim.x + threadIdx.x;
    int st = gridDim.x * blockDim.x;
    for (int i = i0; i < 36864; i += st) {
        int reg  = i & 1;
        int j    = (i >> 1) & 1;
        int lane = (i >> 2) & 31;
        int qq   = (i >> 7) & 3;
        int gate = (i >> 9) % 3;
        int kt   = (i / 1536) % 4;
        int side = (i / 6144) % 2;
        int l    = i / 12288;
        int g = lane >> 2, tg = lane & 3;
        int n = (gate * 8 + qq * 2 + j) * 8 + g;        // column 0..191
        int k0 = kt * 16 + tg * 2 + reg * 8;
        float w0, w1;
        if (side == 1) {
            w0 = w_hh[(l * 192 + n) * 64 + k0];
            w1 = w_hh[(l * 192 + n) * 64 + k0 + 1];
        } else if (l > 0) {
            w0 = w_ih[(l * 192 + n) * 64 + k0];
            w1 = w_ih[(l * 192 + n) * 64 + k0 + 1];
        } else {
            // fused: Wf[n,k] = sum_e Wi0[n,e] * emb_w[e,k]
            float s0 = 0.f, s1 = 0.f;
            for (int e = 0; e < 64; e++) {
                float wi = w_ih[n * 64 + e];
                s0 += wi * emb_w[e * 64 + k0];
                s1 += wi * emb_w[e * 64 + k0 + 1];
            }
            w0 = s0; w1 = s1;
        }
        g_wh[i] = packbf(w0, w1);
    }
    for (int i = i0; i < 3 * 64; i += st) {
        int l = i >> 6, c = i & 63;
        float bfr = 0.f, bfz = 0.f, bfn = 0.f;
        if (l == 0) {
            for (int e = 0; e < 64; e++) {
                float be = emb_b[e];
                bfr += be * w_ih[c * 64 + e];
                bfz += be * w_ih[(64 + c) * 64 + e];
                bfn += be * w_ih[(128 + c) * 64 + e];
            }
        }
        g_bias[l * 256 + c]       = b_ih[l * 192 + c]      + b_hh[l * 192 + c]      + bfr;
        g_bias[l * 256 + 64 + c]  = b_ih[l * 192 + 64 + c] + b_hh[l * 192 + 64 + c] + bfz;
        g_bias[l * 256 + 128 + c] = b_ih[l * 192 + 128 + c] + bfn;
        g_bias[l * 256 + 192 + c] = b_hh[l * 192 + 128 + c];
    }
}

// =============== device helpers ===============
__device__ __forceinline__ u32 smem_u32(const void* p) {
    u32 a;
    asm("{ .reg .u64 t; cvta.to.shared.u64 t, %1; cvt.u32.u64 %0, t; }" : "=r"(a) : "l"(p));
    return a;
}
__device__ __forceinline__ void mma16816(float* d, const u32* a, u32 b0, u32 b1) {
    asm volatile(
        "mma.sync.aligned.m16n8k16.row.col.f32.bf16.bf16.f32 "
        "{%0,%1,%2,%3},{%4,%5,%6,%7},{%8,%9},{%0,%1,%2,%3};"
        : "+f"(d[0]), "+f"(d[1]), "+f"(d[2]), "+f"(d[3])
        : "r"(a[0]), "r"(a[1]), "r"(a[2]), "r"(a[3]), "r"(b0), "r"(b1));
}
__device__ __forceinline__ void lds128(u32* r, u32 a) {
    asm volatile("ld.shared.v4.u32 {%0,%1,%2,%3},[%4];"
                 : "=r"(r[0]), "=r"(r[1]), "=r"(r[2]), "=r"(r[3]) : "r"(a));
}
__device__ __forceinline__ void lds64(u32& x, u32& y, u32 a) {
    asm volatile("ld.shared.v2.u32 {%0,%1},[%2];" : "=r"(x), "=r"(y) : "r"(a));
}
__device__ __forceinline__ void sts64(u32 a, u32 x, u32 y) {
    asm volatile("st.shared.v2.u32 [%0],{%1,%2};" :: "r"(a), "r"(x), "r"(y));
}
__device__ __forceinline__ void cpasync16(u32 s, const void* g) {
    asm volatile("cp.async.ca.shared.global [%0],[%1],16;" :: "r"(s), "l"(g));
}
__device__ __forceinline__ void cpcommit() { asm volatile("cp.async.commit_group;"); }
__device__ __forceinline__ void cpwaitall() { asm volatile("cp.async.wait_group 0;"); }
__device__ __forceinline__ void named_bar(int id) {
    asm volatile("bar.sync %0, 128;" :: "r"(id) : "memory");
}
__device__ __forceinline__ float sigmf(float x) { return __fdividef(1.f, 1.f + __expf(-x)); }
__device__ __forceinline__ float tanhfast(float x) { return 1.f - __fdividef(2.f, __expf(2.f * x) + 1.f); }

// SMEM layout (bytes), 112-row CTA:
//   states S1,S2,S3 (h0,h1,h2) at s*28672 (hi +0, lo +14336) = 86016
//   output partials at SO_P (7mt x 4q x 16 x 2 f32)          = 3584
//   weight double-buffer at SO_W: 2 x 49152                  = 98304
#define SO_P   86016
#define SO_W   89600
#define WBUF   49152
#define SMEMSZ (SO_W + 2 * WBUF)   /* 187904 */

extern "C" __global__ void __launch_bounds__(NTH, 1)
gru_mma_kernel(const float* __restrict__ enc,
               const float* __restrict__ out_w,
               const float* __restrict__ out_b,
               float* __restrict__ out)
{
    extern __shared__ char smc[];
    const u32 sb   = smem_u32(smc);
    const int tid  = threadIdx.x;
    const int lane = tid & 31;
    const int warp = tid >> 5;            // 28 warps
    const int mt   = warp >> 2;           // 7 mtiles x 16 rows
    const int q    = warp & 3;            // column quarter (16 cols of 64)
    const int g    = lane >> 2;
    const int tg   = lane & 3;
    const int row0 = blockIdx.x * MTILE;
    const int barid = 1 + mt;

    // x-source / h-source state index per layer (x of layer0 = h2 = S[2])
    const int xs[3] = {2, 0, 1};
    const int hs[3] = {0, 1, 2};

    // ---- init h0/h1/h2 (states 0..2) frag-linear from enc (guarded rows) ----
    for (int i = tid; i < MTILE * 32; i += NTH) {
        int m = i >> 5, kp = i & 31;
        int k = kp * 2;
        int rr = row0 + m; if (rr > 16383) rr = 16383;
        float v0 = enc[(size_t)rr * 64 + k];
        float v1 = enc[(size_t)rr * 64 + k + 1];
        u32 hi = packbf(v0, v1);
        u32 lo = packbf(v0 - blo(hi), v1 - bhi(hi));
        int kt = k >> 4, kin = k & 15;
        int gg = m & 15;
        int reg = ((kin >= 8) ? 2 : 0) + ((gg >= 8) ? 1 : 0);
        int ln = (gg & 7) * 4 + ((kin & 7) >> 1);
        u32 off = (u32)((m >> 4) * 2048 + kt * 512 + ln * 16 + reg * 4);
        #pragma unroll
        for (int s = 0; s < 3; s++) {
            *(u32*)(smc + s * 28672 + off)         = hi;
            *(u32*)(smc + s * 28672 + 14336 + off) = lo;
        }
    }

    // pre-stage phase 0 (layer 0 weights) into buf 0
    for (int o = tid * 16; o < WBUF; o += NTH * 16)
        cpasync16(sb + SO_W + o, (const char*)g_wh + o);
    cpcommit(); cpwaitall();
    __syncthreads();

    int buf = 0;
    const u32 aoff = (u32)(mt * 2048 + lane * 16);
    float* sp = (float*)(smc + SO_P);

    #pragma unroll 1
    for (int t = 0; t < TSTEPS; t++) {

        #pragma unroll 1
        for (int l = 0; l < 3; l++) {
            // issue prefetch of next phase weights
            {
                int nx = (l + 1) % 3;
                u32 wbn = sb + SO_W + (buf ^ 1) * WBUF;
                const char* src = (const char*)g_wh + nx * 49152;
                for (int o = tid * 16; o < WBUF; o += NTH * 16)
                    cpasync16(wbn + o, src + o);
                cpcommit();
            }

            float aR[2][4], aZ[2][4], aN[2][4], aM[2][4];
            #pragma unroll
            for (int j = 0; j < 2; j++)
                #pragma unroll
                for (int e = 0; e < 4; e++) { aR[j][e]=0.f; aZ[j][e]=0.f; aN[j][e]=0.f; aM[j][e]=0.f; }

            {
                const u32 wb = sb + SO_W + buf * WBUF;
                #pragma unroll
                for (int side = 0; side < 2; side++) {    // 0 = x-side, 1 = h-side
                    const int stA = (side == 0) ? xs[l] : hs[l];
                    const u32 abase = sb + (u32)(stA * 28672) + aoff;
                    const u32 wside = wb + (u32)(side * 24576);
                    #pragma unroll 1
                    for (int kt = 0; kt < 4; kt++) {
                        u32 ah[4], al[4];
                        lds128(ah, abase + (u32)(kt * 512));
                        lds128(al, abase + 14336 + (u32)(kt * 512));
                        #pragma unroll
                        for (int gate = 0; gate < 3; gate++) {
                            float (*acc)[4] = (gate == 0) ? aR :
                                              (gate == 1) ? aZ :
                                              ((side == 0) ? aN : aM);
                            u32 b4[4];
                            lds128(b4, wside + (u32)(((kt * 12 + gate * 4 + q) * 32 + lane) * 16));
                            mma16816(acc[0], ah, b4[0], b4[1]);
                            mma16816(acc[0], al, b4[0], b4[1]);
                            mma16816(acc[1], ah, b4[2], b4[3]);
                            mma16816(acc[1], al, b4[2], b4[3]);
                        }
                    }
                }
            }
            // q-peers' A-loads of this phase must finish before epi rewrites h_l
            named_bar(barid);

            // ---- layer epilogue ----
            const float* gb = g_bias + l * 256;
            const u32 hbase = sb + (u32)(hs[l] * 28672) + aoff;
            float oA0 = 0.f, oA1 = 0.f, oB0 = 0.f, oB1 = 0.f;
            #pragma unroll
            for (int j = 0; j < 2; j++) {
                int ntc = q * 2 + j;
                int c0 = ntc * 8 + 2 * tg;
                float br0 = __ldg(gb + c0),        br1 = __ldg(gb + c0 + 1);
                float bz0 = __ldg(gb + 64 + c0),   bz1 = __ldg(gb + 64 + c0 + 1);
                float bn0 = __ldg(gb + 128 + c0),  bn1 = __ldg(gb + 128 + c0 + 1);
                float bm0 = __ldg(gb + 192 + c0),  bm1 = __ldg(gb + 192 + c0 + 1);
                u32 ad = hbase + (u32)((ntc >> 1) * 512 + (ntc & 1) * 8);
                u32 hh0, hh1, hl0, hl1;
                lds64(hh0, hh1, ad);
                lds64(hl0, hl1, ad + 14336);
                float ho00 = blo(hh0) + blo(hl0), ho01 = bhi(hh0) + bhi(hl0);
                float ho10 = blo(hh1) + blo(hl1), ho11 = bhi(hh1) + bhi(hl1);

                float r, z, n;
                r = sigmf(aR[j][0] + br0); z = sigmf(aZ[j][0] + bz0);
                n = tanhfast(aN[j][0] + bn0 + r * (aM[j][0] + bm0));
                float h00 = n + z * (ho00 - n);
                r = sigmf(aR[j][1] + br1); z = sigmf(aZ[j][1] + bz1);
                n = tanhfast(aN[j][1] + bn1 + r * (aM[j][1] + bm1));
                float h01 = n + z * (ho01 - n);
                r = sigmf(aR[j][2] + br0); z = sigmf(aZ[j][2] + bz0);
                n = tanhfast(aN[j][2] + bn0 + r * (aM[j][2] + bm0));
                float h10 = n + z * (ho10 - n);
                r = sigmf(aR[j][3] + br1); z = sigmf(aZ[j][3] + bz1);
                n = tanhfast(aN[j][3] + bn1 + r * (aM[j][3] + bm1));
                float h11 = n + z * (ho11 - n);

                u32 hi0 = packbf(h00, h01), hi1 = packbf(h10, h11);
                u32 lo0 = packbf(h00 - blo(hi0), h01 - bhi(hi0));
                u32 lo1 = packbf(h10 - blo(hi1), h11 - bhi(hi1));
                sts64(ad, hi0, hi1);
                sts64(ad + 14336, lo0, lo1);

                if (l == 2) {
                    float w00 = __ldg(out_w + c0),      w01 = __ldg(out_w + c0 + 1);
                    float w10 = __ldg(out_w + 64 + c0), w11 = __ldg(out_w + 64 + c0 + 1);
                    oA0 += h00 * w00 + h01 * w01;
                    oA1 += h00 * w10 + h01 * w11;
                    oB0 += h10 * w00 + h11 * w01;
                    oB1 += h10 * w10 + h11 * w11;
                }
            }
            if (l == 2) {
                #pragma unroll
                for (int m = 1; m <= 2; m <<= 1) {
                    oA0 += __shfl_xor_sync(0xffffffffu, oA0, m);
                    oA1 += __shfl_xor_sync(0xffffffffu, oA1, m);
                    oB0 += __shfl_xor_sync(0xffffffffu, oB0, m);
                    oB1 += __shfl_xor_sync(0xffffffffu, oB1, m);
                }
                if (tg == 0) {
                    int base = ((mt * 4 + q) * 16 + g) * 2;
                    sp[base]     = oA0;
                    sp[base + 1] = oA1;
                    int base2 = ((mt * 4 + q) * 16 + g + 8) * 2;
                    sp[base2]     = oB0;
                    sp[base2 + 1] = oB1;
                }
                named_bar(barid);
                if (q == 0) {
                    int row = lane >> 1, j = lane & 1;
                    float v = sp[((mt * 4 + 0) * 16 + row) * 2 + j] +
                              sp[((mt * 4 + 1) * 16 + row) * 2 + j] +
                              sp[((mt * 4 + 2) * 16 + row) * 2 + j] +
                              sp[((mt * 4 + 3) * 16 + row) * 2 + j] + __ldg(out_b + j);
                    int grow = row0 + mt * 16 + row;
                    if (grow < 16384)
                        out[(size_t)grow * (TSTEPS * 2) + t * 2 + j] = v;
                }
            }

            // buffer swap: wait for prefetch + make epi writes visible CTA-wide
            cpwaitall();
            __syncthreads();
            buf ^= 1;
        }
    }
}

extern "C" void kernel_launch(void* const* d_in, const int* in_sizes, int n_in,
                              void* d_out, int out_size)
{
    const float* enc   = (const float*)d_in[0];
    const float* emb_w = (const float*)d_in[1];
    const float* emb_b = (const float*)d_in[2];
    const float* w_ih  = (const float*)d_in[3];
    const float* w_hh  = (const float*)d_in[4];
    const float* b_ih  = (const float*)d_in[5];
    const float* b_hh  = (const float*)d_in[6];
    const float* out_w = (const float*)d_in[7];
    const float* out_b = (const float*)d_in[8];

    cudaFuncSetAttribute(gru_mma_kernel,
                         cudaFuncAttributeMaxDynamicSharedMemorySize, SMEMSZ);

    prep_kernel<<<96, 256>>>(emb_w, emb_b, w_ih, w_hh, b_ih, b_hh);
    gru_mma_kernel<<<152, NTH, SMEMSZ>>>(enc, out_w, out_b, (float*)d_out);
}

// round 13
// speedup vs baseline: 2.3065x; 1.2276x over previous
#include <cuda_runtime.h>
#include <cuda_fp16.h>

typedef unsigned long long u64;
typedef unsigned int u32;

#define TSTEPS 128
#define NTH    896
#define MTILE  112

// =============== prepped weights (global scratch), fp16 ===============
// g_wh layout [l][side][kt(4)][gate(3)][q(4)][lane(32)][j(2)][reg(2)] u32
//   side0 = x-side weights (layer0: fused Wi0@We), side1 = w_hh
__device__ __align__(16) u32 g_wh[3 * 2 * 4 * 3 * 4 * 32 * 2 * 2];   // 36864 u32
// combined biases per layer: [0:64)=bir+bhr(+bf_r) [64:128)=biz+bhz(+bf_z)
//                            [128:192)=bin(+bf_n)  [192:256)=bhn
__device__ __align__(16) float g_bias[3 * 256];

__device__ __forceinline__ u32 packh(float a, float b) {
    __half2 h2 = __floats2half2_rn(a, b);
    return *reinterpret_cast<u32*>(&h2);
}

__global__ void prep_kernel(const float* __restrict__ emb_w,
                            const float* __restrict__ emb_b,
                            const float* __restrict__ w_ih,
                            const float* __restrict__ w_hh,
                            const float* __restrict__ b_ih,
                            const float* __restrict__ b_hh)
{
    int i0 = blockIdx.x * blockDim.x + threadIdx.x;
    int st = gridDim.x * blockDim.x;
    for (int i = i0; i < 36864; i += st) {
        int reg  = i & 1;
        int j    = (i >> 1) & 1;
        int lane = (i >> 2) & 31;
        int qq   = (i >> 7) & 3;
        int gate = (i >> 9) % 3;
        int kt   = (i / 1536) % 4;
        int side = (i / 6144) % 2;
        int l    = i / 12288;
        int g = lane >> 2, tg = lane & 3;
        int n = (gate * 8 + qq * 2 + j) * 8 + g;        // column 0..191
        int k0 = kt * 16 + tg * 2 + reg * 8;
        float w0, w1;
        if (side == 1) {
            w0 = w_hh[(l * 192 + n) * 64 + k0];
            w1 = w_hh[(l * 192 + n) * 64 + k0 + 1];
        } else if (l > 0) {
            w0 = w_ih[(l * 192 + n) * 64 + k0];
            w1 = w_ih[(l * 192 + n) * 64 + k0 + 1];
        } else {
            // fused: Wf[n,k] = sum_e Wi0[n,e] * emb_w[e,k]
            float s0 = 0.f, s1 = 0.f;
            for (int e = 0; e < 64; e++) {
                float wi = w_ih[n * 64 + e];
                s0 += wi * emb_w[e * 64 + k0];
                s1 += wi * emb_w[e * 64 + k0 + 1];
            }
            w0 = s0; w1 = s1;
        }
        g_wh[i] = packh(w0, w1);
    }
    for (int i = i0; i < 3 * 64; i += st) {
        int l = i >> 6, c = i & 63;
        float bfr = 0.f, bfz = 0.f, bfn = 0.f;
        if (l == 0) {
            for (int e = 0; e < 64; e++) {
                float be = emb_b[e];
                bfr += be * w_ih[c * 64 + e];
                bfz += be * w_ih[(64 + c) * 64 + e];
                bfn += be * w_ih[(128 + c) * 64 + e];
            }
        }
        g_bias[l * 256 + c]       = b_ih[l * 192 + c]      + b_hh[l * 192 + c]      + bfr;
        g_bias[l * 256 + 64 + c]  = b_ih[l * 192 + 64 + c] + b_hh[l * 192 + 64 + c] + bfz;
        g_bias[l * 256 + 128 + c] = b_ih[l * 192 + 128 + c] + bfn;
        g_bias[l * 256 + 192 + c] = b_hh[l * 192 + 128 + c];
    }
}

// =============== device helpers ===============
__device__ __forceinline__ u32 smem_u32(const void* p) {
    u32 a;
    asm("{ .reg .u64 t; cvta.to.shared.u64 t, %1; cvt.u32.u64 %0, t; }" : "=r"(a) : "l"(p));
    return a;
}
__device__ __forceinline__ void mma16816h(float* d, const u32* a, u32 b0, u32 b1) {
    asm volatile(
        "mma.sync.aligned.m16n8k16.row.col.f32.f16.f16.f32 "
        "{%0,%1,%2,%3},{%4,%5,%6,%7},{%8,%9},{%0,%1,%2,%3};"
        : "+f"(d[0]), "+f"(d[1]), "+f"(d[2]), "+f"(d[3])
        : "r"(a[0]), "r"(a[1]), "r"(a[2]), "r"(a[3]), "r"(b0), "r"(b1));
}
__device__ __forceinline__ void lds128(u32* r, u32 a) {
    asm volatile("ld.shared.v4.u32 {%0,%1,%2,%3},[%4];"
                 : "=r"(r[0]), "=r"(r[1]), "=r"(r[2]), "=r"(r[3]) : "r"(a));
}
__device__ __forceinline__ void lds128f(float* r, u32 a) {
    asm volatile("ld.shared.v4.f32 {%0,%1,%2,%3},[%4];"
                 : "=f"(r[0]), "=f"(r[1]), "=f"(r[2]), "=f"(r[3]) : "r"(a));
}
__device__ __forceinline__ void sts64(u32 a, u32 x, u32 y) {
    asm volatile("st.shared.v2.u32 [%0],{%1,%2};" :: "r"(a), "r"(x), "r"(y));
}
__device__ __forceinline__ void sts128f(u32 a, float x, float y, float z, float w) {
    asm volatile("st.shared.v4.f32 [%0],{%1,%2,%3,%4};"
                 :: "r"(a), "f"(x), "f"(y), "f"(z), "f"(w));
}
__device__ __forceinline__ void cpasync16(u32 s, const void* g) {
    asm volatile("cp.async.ca.shared.global [%0],[%1],16;" :: "r"(s), "l"(g));
}
__device__ __forceinline__ void cpcommit() { asm volatile("cp.async.commit_group;"); }
__device__ __forceinline__ void cpwaitall() { asm volatile("cp.async.wait_group 0;"); }
__device__ __forceinline__ void named_bar(int id) {
    asm volatile("bar.sync %0, 128;" :: "r"(id) : "memory");
}
__device__ __forceinline__ float sigmf(float x) { return __fdividef(1.f, 1.f + __expf(-x)); }
__device__ __forceinline__ float tanhfast(float x) { return 1.f - __fdividef(2.f, __expf(2.f * x) + 1.f); }

// SMEM layout (bytes), 112-row CTA:
//   fp16 states S0,S1,S2 (h0,h1,h2) at s*14336          = 43008
//   fp32 master states at SM32 + s*28672                = 86016
//   output partials at SO_P (7mt x 4q x 16 x 2 f32)     = 3584
//   weight double-buffer at SO_W: 2 x 49152             = 98304
#define SM32   43008
#define SO_P   129024
#define SO_W   132608
#define WBUF   49152
#define SMEMSZ (SO_W + 2 * WBUF)   /* 230912 */

extern "C" __global__ void __launch_bounds__(NTH, 1)
gru_mma_kernel(const float* __restrict__ enc,
               const float* __restrict__ out_w,
               const float* __restrict__ out_b,
               float* __restrict__ out)
{
    extern __shared__ char smc[];
    const u32 sb   = smem_u32(smc);
    const int tid  = threadIdx.x;
    const int lane = tid & 31;
    const int warp = tid >> 5;            // 28 warps
    const int mt   = warp >> 2;           // 7 mtiles x 16 rows
    const int q    = warp & 3;            // column quarter (16 cols of 64)
    const int g    = lane >> 2;
    const int tg   = lane & 3;
    const int row0 = blockIdx.x * MTILE;
    const int barid = 1 + mt;

    // x-source / h-source state index per layer (x of layer0 = h2 = S[2])
    const int xs[3] = {2, 0, 1};
    const int hs[3] = {0, 1, 2};

    // ---- init fp16 states + fp32 masters from enc (guarded rows) ----
    for (int i = tid; i < MTILE * 32; i += NTH) {
        int m = i >> 5, kp = i & 31;
        int k = kp * 2;
        int rr = row0 + m; if (rr > 16383) rr = 16383;
        float v0 = enc[(size_t)rr * 64 + k];
        float v1 = enc[(size_t)rr * 64 + k + 1];
        u32 h16 = packh(v0, v1);
        int kt = k >> 4, kin = k & 15;
        int gg = m & 15;
        int reg = ((kin >= 8) ? 2 : 0) + ((gg >= 8) ? 1 : 0);
        int ln = (gg & 7) * 4 + ((kin & 7) >> 1);
        u32 off = (u32)((m >> 4) * 2048 + kt * 512 + ln * 16 + reg * 4);
        #pragma unroll
        for (int s = 0; s < 3; s++) {
            *(u32*)(smc + s * 14336 + off) = h16;
            *(float*)(smc + SM32 + s * 28672 + 2 * off)     = v0;
            *(float*)(smc + SM32 + s * 28672 + 2 * off + 4) = v1;
        }
    }

    // pre-stage phase 0 (layer 0 weights) into buf 0
    for (int o = tid * 16; o < WBUF; o += NTH * 16)
        cpasync16(sb + SO_W + o, (const char*)g_wh + o);
    cpcommit(); cpwaitall();
    __syncthreads();

    int buf = 0;
    const u32 aoff = (u32)(mt * 2048 + lane * 16);
    float* sp = (float*)(smc + SO_P);

    #pragma unroll 1
    for (int t = 0; t < TSTEPS; t++) {

        #pragma unroll 1
        for (int l = 0; l < 3; l++) {
            // issue prefetch of next phase weights
            {
                int nx = (l + 1) % 3;
                u32 wbn = sb + SO_W + (buf ^ 1) * WBUF;
                const char* src = (const char*)g_wh + nx * 49152;
                for (int o = tid * 16; o < WBUF; o += NTH * 16)
                    cpasync16(wbn + o, src + o);
                cpcommit();
            }

            float aR[2][4], aZ[2][4], aN[2][4], aM[2][4];
            #pragma unroll
            for (int j = 0; j < 2; j++)
                #pragma unroll
                for (int e = 0; e < 4; e++) { aR[j][e]=0.f; aZ[j][e]=0.f; aN[j][e]=0.f; aM[j][e]=0.f; }

            {
                const u32 wb = sb + SO_W + buf * WBUF;
                #pragma unroll
                for (int side = 0; side < 2; side++) {    // 0 = x-side, 1 = h-side
                    const int stA = (side == 0) ? xs[l] : hs[l];
                    const u32 abase = sb + (u32)(stA * 14336) + aoff;
                    const u32 wside = wb + (u32)(side * 24576);
                    #pragma unroll 1
                    for (int kt = 0; kt < 4; kt++) {
                        u32 ah[4];
                        lds128(ah, abase + (u32)(kt * 512));
                        #pragma unroll
                        for (int gate = 0; gate < 3; gate++) {
                            float (*acc)[4] = (gate == 0) ? aR :
                                              (gate == 1) ? aZ :
                                              ((side == 0) ? aN : aM);
                            u32 b4[4];
                            lds128(b4, wside + (u32)(((kt * 12 + gate * 4 + q) * 32 + lane) * 16));
                            mma16816h(acc[0], ah, b4[0], b4[1]);
                            mma16816h(acc[1], ah, b4[2], b4[3]);
                        }
                    }
                }
            }
            // q-peers' A-loads of this phase must finish before epi rewrites h_l
            named_bar(barid);

            // ---- layer epilogue (fp32 master recurrence) ----
            const float* gb = g_bias + l * 256;
            const u32 hbase16 = sb + (u32)(hs[l] * 14336) + aoff;
            const u32 hbase32 = sb + SM32 + (u32)(hs[l] * 28672) + aoff * 2;
            float oA0 = 0.f, oA1 = 0.f, oB0 = 0.f, oB1 = 0.f;
            #pragma unroll
            for (int j = 0; j < 2; j++) {
                int ntc = q * 2 + j;
                int c0 = ntc * 8 + 2 * tg;
                float br0 = __ldg(gb + c0),        br1 = __ldg(gb + c0 + 1);
                float bz0 = __ldg(gb + 64 + c0),   bz1 = __ldg(gb + 64 + c0 + 1);
                float bn0 = __ldg(gb + 128 + c0),  bn1 = __ldg(gb + 128 + c0 + 1);
                float bm0 = __ldg(gb + 192 + c0),  bm1 = __ldg(gb + 192 + c0 + 1);
                u32 rel = (u32)((ntc >> 1) * 512 + (ntc & 1) * 8);
                u32 ad16 = hbase16 + rel;
                u32 ad32 = hbase32 + rel * 2;
                float ho[4];                      // h_old: {g,c0},{g,c0+1},{g+8,c0},{g+8,c0+1}
                lds128f(ho, ad32);

                float r, z, n;
                r = sigmf(aR[j][0] + br0); z = sigmf(aZ[j][0] + bz0);
                n = tanhfast(aN[j][0] + bn0 + r * (aM[j][0] + bm0));
                float h00 = n + z * (ho[0] - n);
                r = sigmf(aR[j][1] + br1); z = sigmf(aZ[j][1] + bz1);
                n = tanhfast(aN[j][1] + bn1 + r * (aM[j][1] + bm1));
                float h01 = n + z * (ho[1] - n);
                r = sigmf(aR[j][2] + br0); z = sigmf(aZ[j][2] + bz0);
                n = tanhfast(aN[j][2] + bn0 + r * (aM[j][2] + bm0));
                float h10 = n + z * (ho[2] - n);
                r = sigmf(aR[j][3] + br1); z = sigmf(aZ[j][3] + bz1);
                n = tanhfast(aN[j][3] + bn1 + r * (aM[j][3] + bm1));
                float h11 = n + z * (ho[3] - n);

                sts64(ad16, packh(h00, h01), packh(h10, h11));
                sts128f(ad32, h00, h01, h10, h11);

                if (l == 2) {
                    float w00 = __ldg(out_w + c0),      float_w01 = __ldg(out_w + c0 + 1);
                    float w10 = __ldg(out_w + 64 + c0), w11 = __ldg(out_w + 64 + c0 + 1);
                    oA0 += h00 * w00 + h01 * float_w01;
                    oA1 += h00 * w10 + h01 * w11;
                    oB0 += h10 * w00 + h11 * float_w01;
                    oB1 += h10 * w10 + h11 * w11;
                }
            }
            if (l == 2) {
                #pragma unroll
                for (int m = 1; m <= 2; m <<= 1) {
                    oA0 += __shfl_xor_sync(0xffffffffu, oA0, m);
                    oA1 += __shfl_xor_sync(0xffffffffu, oA1, m);
                    oB0 += __shfl_xor_sync(0xffffffffu, oB0, m);
                    oB1 += __shfl_xor_sync(0xffffffffu, oB1, m);
                }
                if (tg == 0) {
                    int base = ((mt * 4 + q) * 16 + g) * 2;
                    sp[base]     = oA0;
                    sp[base + 1] = oA1;
                    int base2 = ((mt * 4 + q) * 16 + g + 8) * 2;
                    sp[base2]     = oB0;
                    sp[base2 + 1] = oB1;
                }
                named_bar(barid);
                if (q == 0) {
                    int row = lane >> 1, j = lane & 1;
                    float v = sp[((mt * 4 + 0) * 16 + row) * 2 + j] +
                              sp[((mt * 4 + 1) * 16 + row) * 2 + j] +
                              sp[((mt * 4 + 2) * 16 + row) * 2 + j] +
                              sp[((mt * 4 + 3) * 16 + row) * 2 + j] + __ldg(out_b + j);
                    int grow = row0 + mt * 16 + row;
                    if (grow < 16384)
                        out[(size_t)grow * (TSTEPS * 2) + t * 2 + j] = v;
                }
            }

            // buffer swap: wait for prefetch + make epi writes visible CTA-wide
            cpwaitall();
            __syncthreads();
            buf ^= 1;
        }
    }
}

extern "C" void kernel_launch(void* const* d_in, const int* in_sizes, int n_in,
                              void* d_out, int out_size)
{
    const float* enc   = (const float*)d_in[0];
    const float* emb_w = (const float*)d_in[1];
    const float* emb_b = (const float*)d_in[2];
    const float* w_ih  = (const float*)d_in[3];
    const float* w_hh  = (const float*)d_in[4];
    const float* b_ih  = (const float*)d_in[5];
    const float* b_hh  = (const float*)d_in[6];
    const float* out_w = (const float*)d_in[7];
    const float* out_b = (const float*)d_in[8];

    cudaFuncSetAttribute(gru_mma_kernel,
                         cudaFuncAttributeMaxDynamicSharedMemorySize, SMEMSZ);

    prep_kernel<<<96, 256>>>(emb_w, emb_b, w_ih, w_hh, b_ih, b_hh);
    gru_mma_kernel<<<152, NTH, SMEMSZ>>>(enc, out_w, out_b, (float*)d_out);
}

// round 14
// speedup vs baseline: 3.5467x; 1.5377x over previous
#include <cuda_runtime.h>
#include <cuda_fp16.h>

typedef unsigned long long u64;
typedef unsigned int u32;

#define TSTEPS 128
#define NTH    896
#define MTILE  112

// =============== prepped weights (global scratch), fp16 ===============
// g_wh layout [l][side][kt(4)][gate(3)][q(4)][lane(32)][j(2)][reg(2)] u32
//   side0 = x-side weights (layer0: fused Wi0@We), side1 = w_hh
__device__ __align__(16) u32 g_wh[3 * 2 * 4 * 3 * 4 * 32 * 2 * 2];   // 36864 u32 = 147456 B
// combined biases per layer: [0:64)=bir+bhr(+bf_r) [64:128)=biz+bhz(+bf_z)
//                            [128:192)=bin(+bf_n)  [192:256)=bhn
__device__ __align__(16) float g_bias[3 * 256];

__device__ __forceinline__ u32 packh(float a, float b) {
    __half2 h2 = __floats2half2_rn(a, b);
    return *reinterpret_cast<u32*>(&h2);
}

__global__ void prep_kernel(const float* __restrict__ emb_w,
                            const float* __restrict__ emb_b,
                            const float* __restrict__ w_ih,
                            const float* __restrict__ w_hh,
                            const float* __restrict__ b_ih,
                            const float* __restrict__ b_hh)
{
    int i0 = blockIdx.x * blockDim.x + threadIdx.x;
    int st = gridDim.x * blockDim.x;
    for (int i = i0; i < 36864; i += st) {
        int reg  = i & 1;
        int j    = (i >> 1) & 1;
        int lane = (i >> 2) & 31;
        int qq   = (i >> 7) & 3;
        int gate = (i >> 9) % 3;
        int kt   = (i / 1536) % 4;
        int side = (i / 6144) % 2;
        int l    = i / 12288;
        int g = lane >> 2, tg = lane & 3;
        int n = (gate * 8 + qq * 2 + j) * 8 + g;        // column 0..191
        int k0 = kt * 16 + tg * 2 + reg * 8;
        float w0, w1;
        if (side == 1) {
            w0 = w_hh[(l * 192 + n) * 64 + k0];
            w1 = w_hh[(l * 192 + n) * 64 + k0 + 1];
        } else if (l > 0) {
            w0 = w_ih[(l * 192 + n) * 64 + k0];
            w1 = w_ih[(l * 192 + n) * 64 + k0 + 1];
        } else {
            // fused: Wf[n,k] = sum_e Wi0[n,e] * emb_w[e,k]
            float s0 = 0.f, s1 = 0.f;
            for (int e = 0; e < 64; e++) {
                float wi = w_ih[n * 64 + e];
                s0 += wi * emb_w[e * 64 + k0];
                s1 += wi * emb_w[e * 64 + k0 + 1];
            }
            w0 = s0; w1 = s1;
        }
        g_wh[i] = packh(w0, w1);
    }
    for (int i = i0; i < 3 * 64; i += st) {
        int l = i >> 6, c = i & 63;
        float bfr = 0.f, bfz = 0.f, bfn = 0.f;
        if (l == 0) {
            for (int e = 0; e < 64; e++) {
                float be = emb_b[e];
                bfr += be * w_ih[c * 64 + e];
                bfz += be * w_ih[(64 + c) * 64 + e];
                bfn += be * w_ih[(128 + c) * 64 + e];
            }
        }
        g_bias[l * 256 + c]       = b_ih[l * 192 + c]      + b_hh[l * 192 + c]      + bfr;
        g_bias[l * 256 + 64 + c]  = b_ih[l * 192 + 64 + c] + b_hh[l * 192 + 64 + c] + bfz;
        g_bias[l * 256 + 128 + c] = b_ih[l * 192 + 128 + c] + bfn;
        g_bias[l * 256 + 192 + c] = b_hh[l * 192 + 128 + c];
    }
}

// =============== device helpers ===============
__device__ __forceinline__ u32 smem_u32(const void* p) {
    u32 a;
    asm("{ .reg .u64 t; cvta.to.shared.u64 t, %1; cvt.u32.u64 %0, t; }" : "=r"(a) : "l"(p));
    return a;
}
__device__ __forceinline__ void mma16816h(float* d, const u32* a, u32 b0, u32 b1) {
    asm volatile(
        "mma.sync.aligned.m16n8k16.row.col.f32.f16.f16.f32 "
        "{%0,%1,%2,%3},{%4,%5,%6,%7},{%8,%9},{%0,%1,%2,%3};"
        : "+f"(d[0]), "+f"(d[1]), "+f"(d[2]), "+f"(d[3])
        : "r"(a[0]), "r"(a[1]), "r"(a[2]), "r"(a[3]), "r"(b0), "r"(b1));
}
__device__ __forceinline__ void lds128(u32* r, u32 a) {
    asm volatile("ld.shared.v4.u32 {%0,%1,%2,%3},[%4];"
                 : "=r"(r[0]), "=r"(r[1]), "=r"(r[2]), "=r"(r[3]) : "r"(a));
}
__device__ __forceinline__ void lds64(u32& x, u32& y, u32 a) {
    asm volatile("ld.shared.v2.u32 {%0,%1},[%2];" : "=r"(x), "=r"(y) : "r"(a));
}
__device__ __forceinline__ void sts64(u32 a, u32 x, u32 y) {
    asm volatile("st.shared.v2.u32 [%0],{%1,%2};" :: "r"(a), "r"(x), "r"(y));
}
__device__ __forceinline__ void cpasync16(u32 s, const void* g) {
    asm volatile("cp.async.ca.shared.global [%0],[%1],16;" :: "r"(s), "l"(g));
}
__device__ __forceinline__ void cpcommit() { asm volatile("cp.async.commit_group;"); }
__device__ __forceinline__ void cpwaitall() { asm volatile("cp.async.wait_group 0;"); }
__device__ __forceinline__ void named_bar(int id) {
    asm volatile("bar.sync %0, 128;" :: "r"(id) : "memory");
}
__device__ __forceinline__ float sigmf(float x) { return __fdividef(1.f, 1.f + __expf(-x)); }
__device__ __forceinline__ float tanhfast(float x) { return 1.f - __fdividef(2.f, __expf(2.f * x) + 1.f); }

// SMEM layout (bytes), 112-row CTA:
//   fp16 states S0,S1,S2 (h0,h1,h2) at s*14336          = 43008
//   output partials at SO_P (7mt x 4q x 16 x 2 f32)     = 3584
//   weights (single resident copy) at SO_W              = 147456
#define SO_P   43008
#define SO_W   46592
#define SMEMSZ (SO_W + 147456)   /* 194048 */

extern "C" __global__ void __launch_bounds__(NTH, 1)
gru_mma_kernel(const float* __restrict__ enc,
               const float* __restrict__ out_w,
               const float* __restrict__ out_b,
               float* __restrict__ out)
{
    extern __shared__ char smc[];
    const u32 sb   = smem_u32(smc);
    const int tid  = threadIdx.x;
    const int lane = tid & 31;
    const int warp = tid >> 5;            // 28 warps
    const int mt   = warp >> 2;           // 7 mtiles x 16 rows
    const int q    = warp & 3;            // column quarter (16 cols of 64)
    const int g    = lane >> 2;
    const int tg   = lane & 3;
    const int row0 = blockIdx.x * MTILE;
    const int barid = 1 + mt;             // per-mt named barrier (128 threads)

    // x-source / h-source state index per layer (x of layer0 = h2 = S[2])
    const int xs[3] = {2, 0, 1};
    const int hs[3] = {0, 1, 2};

    // ---- load ALL weights into SMEM once (resident for the whole run) ----
    for (int o = tid * 16; o < 147456; o += NTH * 16)
        cpasync16(sb + SO_W + o, (const char*)g_wh + o);
    cpcommit();

    // ---- init fp16 states from enc (guarded rows) ----
    for (int i = tid; i < MTILE * 32; i += NTH) {
        int m = i >> 5, kp = i & 31;
        int k = kp * 2;
        int rr = row0 + m; if (rr > 16383) rr = 16383;
        float v0 = enc[(size_t)rr * 64 + k];
        float v1 = enc[(size_t)rr * 64 + k + 1];
        u32 h16 = packh(v0, v1);
        int kt = k >> 4, kin = k & 15;
        int gg = m & 15;
        int reg = ((kin >= 8) ? 2 : 0) + ((gg >= 8) ? 1 : 0);
        int ln = (gg & 7) * 4 + ((kin & 7) >> 1);
        u32 off = (u32)((m >> 4) * 2048 + kt * 512 + ln * 16 + reg * 4);
        #pragma unroll
        for (int s = 0; s < 3; s++)
            *(u32*)(smc + s * 14336 + off) = h16;
    }
    cpwaitall();
    __syncthreads();   // the ONLY CTA-wide barrier; hot loop uses per-mt bars

    const u32 aoff = (u32)(mt * 2048 + lane * 16);
    float* sp = (float*)(smc + SO_P);

    #pragma unroll 1
    for (int t = 0; t < TSTEPS; t++) {

        #pragma unroll 1
        for (int l = 0; l < 3; l++) {

            float aR[2][4], aZ[2][4], aN[2][4], aM[2][4];
            #pragma unroll
            for (int j = 0; j < 2; j++)
                #pragma unroll
                for (int e = 0; e < 4; e++) { aR[j][e]=0.f; aZ[j][e]=0.f; aN[j][e]=0.f; aM[j][e]=0.f; }

            {
                #pragma unroll
                for (int side = 0; side < 2; side++) {    // 0 = x-side, 1 = h-side
                    const int stA = (side == 0) ? xs[l] : hs[l];
                    const u32 abase = sb + (u32)(stA * 14336) + aoff;
                    const u32 wside = sb + SO_W + (u32)(l * 49152 + side * 24576);
                    #pragma unroll 1
                    for (int kt = 0; kt < 4; kt++) {
                        u32 ah[4];
                        lds128(ah, abase + (u32)(kt * 512));
                        #pragma unroll
                        for (int gate = 0; gate < 3; gate++) {
                            float (*acc)[4] = (gate == 0) ? aR :
                                              (gate == 1) ? aZ :
                                              ((side == 0) ? aN : aM);
                            u32 b4[4];
                            lds128(b4, wside + (u32)(((kt * 12 + gate * 4 + q) * 32 + lane) * 16));
                            mma16816h(acc[0], ah, b4[0], b4[1]);
                            mma16816h(acc[1], ah, b4[2], b4[3]);
                        }
                    }
                }
            }
            // q-peers' A-loads of h_l must finish before epilogue rewrites it
            named_bar(barid);

            // ---- layer epilogue (h_old from fp16 state) ----
            const float* gb = g_bias + l * 256;
            const u32 hbase16 = sb + (u32)(hs[l] * 14336) + aoff;
            float oA0 = 0.f, oA1 = 0.f, oB0 = 0.f, oB1 = 0.f;
            #pragma unroll
            for (int j = 0; j < 2; j++) {
                int ntc = q * 2 + j;
                int c0 = ntc * 8 + 2 * tg;
                float br0 = __ldg(gb + c0),        br1 = __ldg(gb + c0 + 1);
                float bz0 = __ldg(gb + 64 + c0),   bz1 = __ldg(gb + 64 + c0 + 1);
                float bn0 = __ldg(gb + 128 + c0),  bn1 = __ldg(gb + 128 + c0 + 1);
                float bm0 = __ldg(gb + 192 + c0),  bm1 = __ldg(gb + 192 + c0 + 1);
                u32 ad16 = hbase16 + (u32)((ntc >> 1) * 512 + (ntc & 1) * 8);
                u32 hh0, hh1;
                lds64(hh0, hh1, ad16);
                float2 hoA = __half22float2(*reinterpret_cast<__half2*>(&hh0));
                float2 hoB = __half22float2(*reinterpret_cast<__half2*>(&hh1));

                float r, z, n;
                r = sigmf(aR[j][0] + br0); z = sigmf(aZ[j][0] + bz0);
                n = tanhfast(aN[j][0] + bn0 + r * (aM[j][0] + bm0));
                float h00 = n + z * (hoA.x - n);
                r = sigmf(aR[j][1] + br1); z = sigmf(aZ[j][1] + bz1);
                n = tanhfast(aN[j][1] + bn1 + r * (aM[j][1] + bm1));
                float h01 = n + z * (hoA.y - n);
                r = sigmf(aR[j][2] + br0); z = sigmf(aZ[j][2] + bz0);
                n = tanhfast(aN[j][2] + bn0 + r * (aM[j][2] + bm0));
                float h10 = n + z * (hoB.x - n);
                r = sigmf(aR[j][3] + br1); z = sigmf(aZ[j][3] + bz1);
                n = tanhfast(aN[j][3] + bn1 + r * (aM[j][3] + bm1));
                float h11 = n + z * (hoB.y - n);

                sts64(ad16, packh(h00, h01), packh(h10, h11));

                if (l == 2) {
                    float w00 = __ldg(out_w + c0),      w01 = __ldg(out_w + c0 + 1);
                    float w10 = __ldg(out_w + 64 + c0), w11 = __ldg(out_w + 64 + c0 + 1);
                    oA0 += h00 * w00 + h01 * w01;
                    oA1 += h00 * w10 + h01 * w11;
                    oB0 += h10 * w00 + h11 * w01;
                    oB1 += h10 * w10 + h11 * w11;
                }
            }
            if (l == 2) {
                #pragma unroll
                for (int m = 1; m <= 2; m <<= 1) {
                    oA0 += __shfl_xor_sync(0xffffffffu, oA0, m);
                    oA1 += __shfl_xor_sync(0xffffffffu, oA1, m);
                    oB0 += __shfl_xor_sync(0xffffffffu, oB0, m);
                    oB1 += __shfl_xor_sync(0xffffffffu, oB1, m);
                }
                if (tg == 0) {
                    int base = ((mt * 4 + q) * 16 + g) * 2;
                    sp[base]     = oA0;
                    sp[base + 1] = oA1;
                    int base2 = ((mt * 4 + q) * 16 + g + 8) * 2;
                    sp[base2]     = oB0;
                    sp[base2 + 1] = oB1;
                }
            }

            // epilogue state writes (and partials) visible to mt peers
            named_bar(barid);

            if (l == 2 && q == 0) {
                int row = lane >> 1, j = lane & 1;
                float v = sp[((mt * 4 + 0) * 16 + row) * 2 + j] +
                          sp[((mt * 4 + 1) * 16 + row) * 2 + j] +
                          sp[((mt * 4 + 2) * 16 + row) * 2 + j] +
                          sp[((mt * 4 + 3) * 16 + row) * 2 + j] + __ldg(out_b + j);
                int grow = row0 + mt * 16 + row;
                if (grow < 16384)
                    out[(size_t)grow * (TSTEPS * 2) + t * 2 + j] = v;
            }
        }
    }
}

extern "C" void kernel_launch(void* const* d_in, const int* in_sizes, int n_in,
                              void* d_out, int out_size)
{
    const float* enc   = (const float*)d_in[0];
    const float* emb_w = (const float*)d_in[1];
    const float* emb_b = (const float*)d_in[2];
    const float* w_ih  = (const float*)d_in[3];
    const float* w_hh  = (const float*)d_in[4];
    const float* b_ih  = (const float*)d_in[5];
    const float* b_hh  = (const float*)d_in[6];
    const float* out_w = (const float*)d_in[7];
    const float* out_b = (const float*)d_in[8];

    cudaFuncSetAttribute(gru_mma_kernel,
                         cudaFuncAttributeMaxDynamicSharedMemorySize, SMEMSZ);

    prep_kernel<<<96, 256>>>(emb_w, emb_b, w_ih, w_hh, b_ih, b_hh);
    gru_mma_kernel<<<152, NTH, SMEMSZ>>>(enc, out_w, out_b, (float*)d_out);
}